// round 6
// baseline (speedup 1.0000x reference)
#include <cuda_runtime.h>
#include <cuda_bf16.h>
#include <stdint.h>

#define B_   4
#define L_   2048
#define D_   1024
#define H_   16
#define DK_  64
#define HD_  1024
#define MROWS_ 8192
#define LN_EPS_ 1e-5f

// ---------------------------------------------------------------------------
// Scratch (device globals; no runtime allocation allowed)
// Packed split-bf16 layout: [M][K/32][32 hi bf16 | 32 lo bf16]  (128B per chunk)
// ---------------------------------------------------------------------------
__device__ __align__(256) uint8_t g_qpk [(long long)MROWS_ * D_ * 4];
__device__ __align__(256) uint8_t g_kpk [(long long)MROWS_ * D_ * 4];
__device__ __align__(256) uint8_t g_vpk [(long long)MROWS_ * D_ * 4];
__device__ __align__(256) uint8_t g_wqpk[(long long)HD_ * D_ * 4];
__device__ __align__(256) uint8_t g_wkpk[(long long)HD_ * D_ * 4];
__device__ __align__(256) uint8_t g_wvpk[(long long)HD_ * D_ * 4];
__device__ __align__(256) uint8_t g_wopk[(long long)D_ * HD_ * 4];
__device__ __align__(256) uint8_t g_qhpk[(long long)MROWS_ * HD_ * 4];
__device__ __align__(256) uint8_t g_khpk[(long long)MROWS_ * HD_ * 4];
__device__ __align__(256) uint8_t g_vTpk[(long long)B_ * H_ * DK_ * L_ * 4];
__device__ __align__(256) uint8_t g_oapk[(long long)MROWS_ * HD_ * 4];
__device__ float g_vh[MROWS_ * HD_];
__device__ float g_op[MROWS_ * HD_];

// ---------------------------------------------------------------------------
// helpers
// ---------------------------------------------------------------------------
__device__ __forceinline__ uint32_t smem_u32(const void* p) {
    uint32_t a;
    asm("{ .reg .u64 t; cvta.to.shared.u64 t, %1; cvt.u32.u64 %0, t; }" : "=r"(a) : "l"(p));
    return a;
}
__device__ __forceinline__ uint32_t sw128(uint32_t off) {
    return off ^ ((off >> 3) & 0x70);
}
__device__ __forceinline__ void cpa16(uint32_t dst, const void* src) {
    asm volatile("cp.async.cg.shared.global [%0], [%1], 16;" :: "r"(dst), "l"(src));
}
#define CP_COMMIT() asm volatile("cp.async.commit_group;" ::: "memory")
#define CP_WAIT0()  asm volatile("cp.async.wait_group 0;" ::: "memory")
#define CP_WAIT1()  asm volatile("cp.async.wait_group 1;" ::: "memory")
#define LDSM_X4(r0, r1, r2, r3, addr)                                      \
    asm volatile("ldmatrix.sync.aligned.m8n8.x4.shared.b16 "               \
                 "{%0,%1,%2,%3}, [%4];"                                    \
                 : "=r"(r0), "=r"(r1), "=r"(r2), "=r"(r3) : "r"(addr))

__device__ __forceinline__ void mma16816(float* d, const uint32_t* a, const uint32_t* b) {
    asm volatile(
        "mma.sync.aligned.m16n8k16.row.col.f32.bf16.bf16.f32 "
        "{%0,%1,%2,%3}, {%4,%5,%6,%7}, {%8,%9}, {%0,%1,%2,%3};"
        : "+f"(d[0]), "+f"(d[1]), "+f"(d[2]), "+f"(d[3])
        : "r"(a[0]), "r"(a[1]), "r"(a[2]), "r"(a[3]), "r"(b[0]), "r"(b[1]));
}

// pack 2 fp32 -> hi bf162 at p, lo bf162 at p+64
__device__ __forceinline__ void pack_store2(uint8_t* p, float v0, float v1) {
    __nv_bfloat162 h = __floats2bfloat162_rn(v0, v1);
    float2 f = __bfloat1622float2(h);
    __nv_bfloat162 l = __floats2bfloat162_rn(v0 - f.x, v1 - f.y);
    *(uint32_t*)p = *(uint32_t*)&h;
    *(uint32_t*)(p + 64) = *(uint32_t*)&l;
}
__device__ __forceinline__ void pack_store4(uint8_t* p, float4 v) {
    __nv_bfloat162 h0 = __floats2bfloat162_rn(v.x, v.y);
    __nv_bfloat162 h1 = __floats2bfloat162_rn(v.z, v.w);
    float2 f0 = __bfloat1622float2(h0), f1 = __bfloat1622float2(h1);
    __nv_bfloat162 l0 = __floats2bfloat162_rn(v.x - f0.x, v.y - f0.y);
    __nv_bfloat162 l1 = __floats2bfloat162_rn(v.z - f1.x, v.w - f1.y);
    uint2 hu, lu;
    hu.x = *(uint32_t*)&h0; hu.y = *(uint32_t*)&h1;
    lu.x = *(uint32_t*)&l0; lu.y = *(uint32_t*)&l1;
    *(uint2*)p = hu;
    *(uint2*)(p + 64) = lu;
}
// split pair of fp32 into hi/lo bf16x2 register form
__device__ __forceinline__ void split2(float a, float b, uint32_t& hi, uint32_t& lo) {
    __nv_bfloat162 h = __floats2bfloat162_rn(a, b);
    float2 f = __bfloat1622float2(h);
    __nv_bfloat162 l = __floats2bfloat162_rn(a - f.x, b - f.y);
    hi = *(uint32_t*)&h;
    lo = *(uint32_t*)&l;
}

// ---------------------------------------------------------------------------
// pack fp32 [M,K] -> packed split bf16
// ---------------------------------------------------------------------------
__global__ void __launch_bounds__(256)
pack_split(const float* __restrict__ src, uint8_t* __restrict__ dst, int K)
{
    const long long idx = (long long)blockIdx.x * 256 + threadIdx.x;
    const int perRow = K >> 2;
    const long long m = idx / perRow;
    const int j = (int)(idx - m * perRow);
    float4 v = *(const float4*)(src + m * K + j * 4);
    const int e0 = j * 4;
    uint8_t* p = dst + (m * (K >> 5) + (e0 >> 5)) * 128 + (e0 & 31) * 2;
    pack_store4(p, v);
}

// ---------------------------------------------------------------------------
// Packed split-bf16 GEMM. 128x64 tile, 8 warps (2x4), 2 CTAs/SM.
// MODE 0: C fp32 + bias.  MODE 1: C packed + bias.
// ---------------------------------------------------------------------------
template<int MODE>
__global__ void __launch_bounds__(256, 2)
pk_gemm(const uint8_t* Apk, const uint8_t* __restrict__ Bpk,
        const float* __restrict__ bias,
        float* Cf, uint8_t* Cpk,
        int nchunks, long long ldA, long long ldB, int ldc, long long ldCpk)
{
    extern __shared__ uint8_t dyn_raw[];
    __shared__ float s_bias[64];

    const int tid = threadIdx.x, wid = tid >> 5, lane = tid & 31;
    const long long m0 = (long long)blockIdx.y * 128;
    const long long n0 = (long long)blockIdx.x * 64;

    uint32_t raw = smem_u32(dyn_raw);
    uint32_t base = (raw + 1023u) & ~1023u;
    const uint32_t aSu[2] = { base, base + 24576 };
    const uint32_t bSu[2] = { base + 16384, base + 24576 + 16384 };

    if (tid < 64) s_bias[tid] = bias ? bias[n0 + tid] : 0.0f;

    float acc[4][2][4];
#pragma unroll
    for (int i = 0; i < 4; i++)
#pragma unroll
        for (int j = 0; j < 2; j++)
#pragma unroll
            for (int e = 0; e < 4; e++) acc[i][j][e] = 0.0f;

    const uint32_t a_row = (uint32_t)((lane & 7) + (lane & 8));
    const uint32_t a_kof = (uint32_t)(((lane >> 4) & 1) * 16);
    const uint32_t b_row = (uint32_t)((lane & 7) + ((lane >> 4) & 1) * 8);
    const uint32_t b_kof = (uint32_t)(((lane >> 3) & 1) * 16);
    const int wm = (wid & 1) * 64;
    const int wn = (wid >> 1) * 16;

    auto prefetch = [&](int s, int c) {
        const uint8_t* Ab = Apk + (long long)c * 128;
#pragma unroll
        for (int i = 0; i < 4; i++) {
            const int idx = i * 256 + tid, row = idx >> 3, g = idx & 7;
            cpa16(aSu[s] + sw128((uint32_t)(row * 128 + g * 16)),
                  Ab + (m0 + row) * ldA + g * 16);
        }
        const uint8_t* Bb = Bpk + (long long)c * 128;
#pragma unroll
        for (int i = 0; i < 2; i++) {
            const int idx = i * 256 + tid, row = idx >> 3, g = idx & 7;
            cpa16(bSu[s] + sw128((uint32_t)(row * 128 + g * 16)),
                  Bb + (n0 + row) * ldB + g * 16);
        }
        CP_COMMIT();
    };

    prefetch(0, 0);
    int cur = 0;
    for (int c = 0; c < nchunks; c++) {
        if (c + 1 < nchunks) {
            prefetch(cur ^ 1, c + 1);
            CP_WAIT1();
        } else {
            CP_WAIT0();
        }
        __syncthreads();

        const uint32_t aS = aSu[cur], bS = bSu[cur];
#pragma unroll
        for (int ks = 0; ks < 2; ks++) {
            uint32_t ah[4][4], al[4][4], bh[2][2], bl[2][2];
#pragma unroll
            for (int mt = 0; mt < 4; mt++) {
                uint32_t off = (uint32_t)(wm + mt * 16 + a_row) * 128 + ks * 32 + a_kof;
                LDSM_X4(ah[mt][0], ah[mt][1], ah[mt][2], ah[mt][3], aS + sw128(off));
            }
            {
                uint32_t r0, r1, r2, r3;
                uint32_t off = (uint32_t)(wn + b_row) * 128 + ks * 32 + b_kof;
                LDSM_X4(r0, r1, r2, r3, bS + sw128(off));
                bh[0][0] = r0; bh[0][1] = r1; bh[1][0] = r2; bh[1][1] = r3;
            }
#pragma unroll
            for (int mt = 0; mt < 4; mt++)
#pragma unroll
                for (int nt = 0; nt < 2; nt++)
                    mma16816(acc[mt][nt], ah[mt], bh[nt]);
            {
                uint32_t r0, r1, r2, r3;
                uint32_t off = (uint32_t)(wn + b_row) * 128 + 64 + ks * 32 + b_kof;
                LDSM_X4(r0, r1, r2, r3, bS + sw128(off));
                bl[0][0] = r0; bl[0][1] = r1; bl[1][0] = r2; bl[1][1] = r3;
            }
#pragma unroll
            for (int mt = 0; mt < 4; mt++)
#pragma unroll
                for (int nt = 0; nt < 2; nt++)
                    mma16816(acc[mt][nt], ah[mt], bl[nt]);
#pragma unroll
            for (int mt = 0; mt < 4; mt++) {
                uint32_t off = (uint32_t)(wm + mt * 16 + a_row) * 128 + 64 + ks * 32 + a_kof;
                LDSM_X4(al[mt][0], al[mt][1], al[mt][2], al[mt][3], aS + sw128(off));
            }
#pragma unroll
            for (int mt = 0; mt < 4; mt++)
#pragma unroll
                for (int nt = 0; nt < 2; nt++)
                    mma16816(acc[mt][nt], al[mt], bh[nt]);
        }
        __syncthreads();
        cur ^= 1;
    }

    const int g = lane >> 2, t = lane & 3;
    if (MODE == 1) {
#pragma unroll
        for (int mt = 0; mt < 4; mt++) {
#pragma unroll
            for (int nt = 0; nt < 2; nt++) {
                const int colw = wn + nt * 8 + 2 * t;
                const long long row0 = m0 + wm + mt * 16 + g;
                const float b0 = s_bias[colw], b1 = s_bias[colw + 1];
                const long long colg = n0 + colw;
                const long long ch = colg >> 5;
                const int wi = (int)(colg & 31);
                pack_store2(Cpk + row0 * ldCpk + ch * 128 + wi * 2,
                            acc[mt][nt][0] + b0, acc[mt][nt][1] + b1);
                pack_store2(Cpk + (row0 + 8) * ldCpk + ch * 128 + wi * 2,
                            acc[mt][nt][2] + b0, acc[mt][nt][3] + b1);
            }
        }
    } else {
#pragma unroll
        for (int mt = 0; mt < 4; mt++) {
#pragma unroll
            for (int nt = 0; nt < 2; nt++) {
                const int colw = wn + nt * 8 + 2 * t;
                const float b0 = s_bias[colw], b1 = s_bias[colw + 1];
                const long long row0 = m0 + wm + mt * 16 + g;
                *(float2*)(Cf + row0 * (long long)ldc + n0 + colw) =
                    make_float2(acc[mt][nt][0] + b0, acc[mt][nt][1] + b1);
                *(float2*)(Cf + (row0 + 8) * (long long)ldc + n0 + colw) =
                    make_float2(acc[mt][nt][2] + b0, acc[mt][nt][3] + b1);
            }
        }
    }
}

// ---------------------------------------------------------------------------
// S-tile compute: sacc[16][4] = Q(16x64) @ K(128x64)^T  (split-bf16, 3 passes)
// ---------------------------------------------------------------------------
__device__ __forceinline__ void compute_S(
    float (*sacc)[4], const uint32_t (*qh4)[4], const uint32_t (*ql4)[4],
    uint32_t ksb, uint32_t b_row, uint32_t b_kof)
{
#pragma unroll
    for (int i = 0; i < 16; i++)
#pragma unroll
        for (int e = 0; e < 4; e++) sacc[i][e] = 0.0f;
#pragma unroll
    for (int f = 0; f < 4; f++) {
#pragma unroll
        for (int j = 0; j < 8; j++) {
            uint32_t rc = (uint32_t)(16 * j + b_row) * 2 + (f >> 1);
            uint32_t offh = rc * 128 + (f & 1) * 32 + b_kof;
            uint32_t h0, h1, h2, h3, l0, l1, l2, l3;
            LDSM_X4(h0, h1, h2, h3, ksb + sw128(offh));
            LDSM_X4(l0, l1, l2, l3, ksb + sw128(offh + 64));
            uint32_t bh0[2] = { h0, h1 }, bh1[2] = { h2, h3 };
            uint32_t bl0[2] = { l0, l1 }, bl1[2] = { l2, l3 };
            mma16816(sacc[2 * j],     qh4[f], bh0);
            mma16816(sacc[2 * j + 1], qh4[f], bh1);
            mma16816(sacc[2 * j],     qh4[f], bl0);
            mma16816(sacc[2 * j + 1], qh4[f], bl1);
            mma16816(sacc[2 * j],     ql4[f], bh0);
            mma16816(sacc[2 * j + 1], ql4[f], bh1);
        }
    }
}

// ---------------------------------------------------------------------------
// Fused attention: per CTA = (b,h, 128 q rows).
// Phase 1: rowsums of exp(S/8).  Phase 2: recompute S, write normalized fp32 P
// to attn (the required output), accumulate O = Pn @ V, emit O packed.
// ---------------------------------------------------------------------------
__global__ void __launch_bounds__(256, 1)
fused_attn(const uint8_t* __restrict__ qhpk, const uint8_t* __restrict__ khpk,
           const uint8_t* __restrict__ vTpk, float* __restrict__ attn,
           uint8_t* __restrict__ oapk)
{
    extern __shared__ uint8_t dyn_raw[];
    const int tid = threadIdx.x, wid = tid >> 5, lane = tid & 31;
    const int bh = blockIdx.x, qb = blockIdx.y;
    const int b = bh >> 4, h = bh & 15;

    uint32_t raw = smem_u32(dyn_raw);
    uint32_t base = (raw + 1023u) & ~1023u;
    const uint32_t qS = base;
    const uint32_t kS[2] = { base + 32768, base + 65536 };
    const uint32_t vS[2] = { base + 98304, base + 131072 };

    const uint8_t* Qg = qhpk + ((long long)b * L_ + qb * 128) * 4096 + h * 256;
    const uint8_t* Kg = khpk + ((long long)b * L_) * 4096 + h * 256;
    const uint8_t* Vg = vTpk + (long long)bh * 64 * 8192;
    float* Pout = attn + ((long long)(h * B_ + b) * L_ + qb * 128) * L_;

    // Q tile load (32KB, once)
#pragma unroll
    for (int i = 0; i < 8; i++) {
        int idx = i * 256 + tid, rc = idx >> 3, g = idx & 7;
        cpa16(qS + sw128((uint32_t)(rc * 128 + g * 16)),
              Qg + (long long)(rc >> 1) * 4096 + (rc & 1) * 128 + g * 16);
    }
    CP_COMMIT();

    auto loadK = [&](int s, int c) {
#pragma unroll
        for (int i = 0; i < 8; i++) {
            int idx = i * 256 + tid, rc = idx >> 3, g = idx & 7;
            cpa16(kS[s] + sw128((uint32_t)(rc * 128 + g * 16)),
                  Kg + ((long long)c * 128 + (rc >> 1)) * 4096 + (rc & 1) * 128 + g * 16);
        }
    };
    auto loadV = [&](int s, int c) {
#pragma unroll
        for (int i = 0; i < 8; i++) {
            int idx = i * 256 + tid, rc = idx >> 3, g = idx & 7;
            cpa16(vS[s] + sw128((uint32_t)(rc * 128 + g * 16)),
                  Vg + (long long)(rc >> 2) * 8192 + (c * 4 + (rc & 3)) * 128 + g * 16);
        }
    };

    const uint32_t a_row = (uint32_t)((lane & 7) + (lane & 8));
    const uint32_t a_kof = (uint32_t)(((lane >> 4) & 1) * 16);
    const uint32_t b_row = (uint32_t)((lane & 7) + ((lane >> 4) & 1) * 8);
    const uint32_t b_kof = (uint32_t)(((lane >> 3) & 1) * 16);

    CP_WAIT0();
    __syncthreads();

    // Q fragments (per warp: rows 16*wid..+15, k 0..63)
    uint32_t qh4[4][4], ql4[4][4];
#pragma unroll
    for (int f = 0; f < 4; f++) {
        uint32_t rc = (uint32_t)(16 * wid + a_row) * 2 + (f >> 1);
        uint32_t offh = rc * 128 + (f & 1) * 32 + a_kof;
        LDSM_X4(qh4[f][0], qh4[f][1], qh4[f][2], qh4[f][3], qS + sw128(offh));
        LDSM_X4(ql4[f][0], ql4[f][1], ql4[f][2], ql4[f][3], qS + sw128(offh + 64));
    }

    // ---------------- Phase 1: rowsums ----------------
    loadK(0, 0);
    CP_COMMIT();
    float rs0 = 0.0f, rs1 = 0.0f;
    for (int c = 0; c < 16; c++) {
        const int cur = c & 1;
        if (c < 15) { loadK(cur ^ 1, c + 1); CP_COMMIT(); CP_WAIT1(); }
        else        { CP_WAIT0(); }
        __syncthreads();

        float sacc[16][4];
        compute_S(sacc, qh4, ql4, kS[cur], b_row, b_kof);
#pragma unroll
        for (int nt = 0; nt < 16; nt++) {
            rs0 += __expf(sacc[nt][0] * 0.125f) + __expf(sacc[nt][1] * 0.125f);
            rs1 += __expf(sacc[nt][2] * 0.125f) + __expf(sacc[nt][3] * 0.125f);
        }
        __syncthreads();
    }
    rs0 += __shfl_xor_sync(0xffffffffu, rs0, 1);
    rs0 += __shfl_xor_sync(0xffffffffu, rs0, 2);
    rs1 += __shfl_xor_sync(0xffffffffu, rs1, 1);
    rs1 += __shfl_xor_sync(0xffffffffu, rs1, 2);
    const float inv0 = 1.0f / rs0;
    const float inv1 = 1.0f / rs1;

    // ---------------- Phase 2: P write + O accumulate ----------------
    loadK(0, 0); loadV(0, 0);
    CP_COMMIT();
    float oacc[8][4];
#pragma unroll
    for (int i = 0; i < 8; i++)
#pragma unroll
        for (int e = 0; e < 4; e++) oacc[i][e] = 0.0f;

    const int g = lane >> 2, t = lane & 3;
    for (int c = 0; c < 16; c++) {
        const int cur = c & 1;
        if (c < 15) { loadK(cur ^ 1, c + 1); loadV(cur ^ 1, c + 1); CP_COMMIT(); CP_WAIT1(); }
        else        { CP_WAIT0(); }
        __syncthreads();

        float sacc[16][4];
        compute_S(sacc, qh4, ql4, kS[cur], b_row, b_kof);

        // exp + normalize + write fp32 P + pack to A-fragments
        uint32_t ph[8][4], pl[8][4];
        float* Prow0 = Pout + (long long)(16 * wid + g) * L_ + c * 128;
        float* Prow1 = Prow0 + 8LL * L_;
#pragma unroll
        for (int f = 0; f < 8; f++) {
            float e0a = __expf(sacc[2 * f][0] * 0.125f) * inv0;
            float e1a = __expf(sacc[2 * f][1] * 0.125f) * inv0;
            float e2a = __expf(sacc[2 * f][2] * 0.125f) * inv1;
            float e3a = __expf(sacc[2 * f][3] * 0.125f) * inv1;
            float e0b = __expf(sacc[2 * f + 1][0] * 0.125f) * inv0;
            float e1b = __expf(sacc[2 * f + 1][1] * 0.125f) * inv0;
            float e2b = __expf(sacc[2 * f + 1][2] * 0.125f) * inv1;
            float e3b = __expf(sacc[2 * f + 1][3] * 0.125f) * inv1;
            *(float2*)(Prow0 + 16 * f + 2 * t)     = make_float2(e0a, e1a);
            *(float2*)(Prow1 + 16 * f + 2 * t)     = make_float2(e2a, e3a);
            *(float2*)(Prow0 + 16 * f + 8 + 2 * t) = make_float2(e0b, e1b);
            *(float2*)(Prow1 + 16 * f + 8 + 2 * t) = make_float2(e2b, e3b);
            split2(e0a, e1a, ph[f][0], pl[f][0]);
            split2(e2a, e3a, ph[f][1], pl[f][1]);
            split2(e0b, e1b, ph[f][2], pl[f][2]);
            split2(e2b, e3b, ph[f][3], pl[f][3]);
        }

        // O += Pn @ V   (B = V^T tile [64 d][128 l] packed)
        const uint32_t vsb = vS[cur];
#pragma unroll
        for (int f = 0; f < 8; f++) {
#pragma unroll
            for (int j = 0; j < 4; j++) {
                uint32_t rc = (uint32_t)(16 * j + b_row) * 4 + (f >> 1);
                uint32_t offh = rc * 128 + (f & 1) * 32 + b_kof;
                uint32_t h0, h1, h2, h3, l0, l1, l2, l3;
                LDSM_X4(h0, h1, h2, h3, vsb + sw128(offh));
                LDSM_X4(l0, l1, l2, l3, vsb + sw128(offh + 64));
                uint32_t vh0[2] = { h0, h1 }, vh1[2] = { h2, h3 };
                uint32_t vl0[2] = { l0, l1 }, vl1[2] = { l2, l3 };
                mma16816(oacc[2 * j],     ph[f], vh0);
                mma16816(oacc[2 * j + 1], ph[f], vh1);
                mma16816(oacc[2 * j],     ph[f], vl0);
                mma16816(oacc[2 * j + 1], ph[f], vl1);
                mma16816(oacc[2 * j],     pl[f], vh0);
                mma16816(oacc[2 * j + 1], pl[f], vh1);
            }
        }
        __syncthreads();
    }

    // O write: packed for o-proj. Rows b*L + qb*128 + 16w + g(+8), cols h*64+d
    const long long mrow = (long long)b * L_ + qb * 128 + 16 * wid + g;
#pragma unroll
    for (int nt = 0; nt < 8; nt++) {
        const int dg = h * 64 + 8 * nt + 2 * t;
        uint8_t* p0 = oapk + mrow * 4096 + (dg >> 5) * 128 + (dg & 31) * 2;
        uint8_t* p1 = oapk + (mrow + 8) * 4096 + (dg >> 5) * 128 + (dg & 31) * 2;
        pack_store2(p0, oacc[nt][0], oacc[nt][1]);
        pack_store2(p1, oacc[nt][2], oacc[nt][3]);
    }
}

// ---------------------------------------------------------------------------
// V transpose: vh fp32 [B,L,H,DK] -> vT packed [(b*H+h)][dk][L/32][128B]
// ---------------------------------------------------------------------------
__global__ void __launch_bounds__(256)
transpose_v_pk(const float* __restrict__ vh, uint8_t* __restrict__ vT)
{
    __shared__ float tsm[32][33];
    const int bh = blockIdx.z;
    const int b = bh >> 4, h = bh & 15;
    const int l0 = blockIdx.x * 32;
    const int d0 = blockIdx.y * 32;
    const int tid = threadIdx.x;
    const int tx = tid & 31;
    const int ty = tid >> 5;

    const float* src = vh + ((long long)b * L_ + l0) * HD_ + h * DK_ + d0;
#pragma unroll
    for (int i = 0; i < 32; i += 8)
        tsm[ty + i][tx] = src[(long long)(ty + i) * HD_ + tx];
    __syncthreads();

    const int lp = tid & 15;
#pragma unroll
    for (int it = 0; it < 2; it++) {
        const int d = (tid >> 4) + 16 * it;
        uint8_t* p = vT + ((long long)bh * 64 + d0 + d) * (L_ / 32 * 128)
                        + (l0 >> 5) * 128 + lp * 4;
        pack_store2(p, tsm[2 * lp][d], tsm[2 * lp + 1][d]);
    }
}

// ---------------------------------------------------------------------------
// LayerNorm + residual
// ---------------------------------------------------------------------------
__global__ void __launch_bounds__(256)
ln_residual(const float* __restrict__ x, const float* __restrict__ res,
            const float* __restrict__ gam, const float* __restrict__ bet,
            float* __restrict__ out)
{
    const long long row = blockIdx.x;
    const float4* x4 = (const float4*)(x   + row * D_);
    const float4* r4 = (const float4*)(res + row * D_);
    const int tid = threadIdx.x;

    float4 v = x4[tid];
    float s  = (v.x + v.y) + (v.z + v.w);
    float sq = (v.x * v.x + v.y * v.y) + (v.z * v.z + v.w * v.w);
#pragma unroll
    for (int o = 16; o > 0; o >>= 1) {
        s  += __shfl_xor_sync(0xffffffffu, s,  o);
        sq += __shfl_xor_sync(0xffffffffu, sq, o);
    }
    __shared__ float ss[8], sqs[8];
    if ((tid & 31) == 0) { ss[tid >> 5] = s; sqs[tid >> 5] = sq; }
    __syncthreads();
    s  = (ss[0]  + ss[1])  + (ss[2]  + ss[3])  + (ss[4]  + ss[5])  + (ss[6]  + ss[7]);
    sq = (sqs[0] + sqs[1]) + (sqs[2] + sqs[3]) + (sqs[4] + sqs[5]) + (sqs[6] + sqs[7]);

    const float mean = s * (1.0f / D_);
    float var = sq * (1.0f / D_) - mean * mean;
    var = fmaxf(var, 0.0f);
    const float rstd = rsqrtf(var + LN_EPS_);

    float4 g  = ((const float4*)gam)[tid];
    float4 bt = ((const float4*)bet)[tid];
    float4 r  = r4[tid];
    float4 o;
    o.x = (v.x - mean) * rstd * g.x + bt.x + r.x;
    o.y = (v.y - mean) * rstd * g.y + bt.y + r.y;
    o.z = (v.z - mean) * rstd * g.z + bt.z + r.z;
    o.w = (v.w - mean) * rstd * g.w + bt.w + r.w;
    ((float4*)(out + row * D_))[tid] = o;
}

// ---------------------------------------------------------------------------
// Launch
// ---------------------------------------------------------------------------
extern "C" void kernel_launch(void* const* d_in, const int* in_sizes, int n_in,
                              void* d_out, int out_size)
{
    (void)in_sizes; (void)n_in; (void)out_size;
    const float* q  = (const float*)d_in[0];
    const float* k  = (const float*)d_in[1];
    const float* v  = (const float*)d_in[2];
    const float* wq = (const float*)d_in[3];
    const float* bq = (const float*)d_in[4];
    const float* wk = (const float*)d_in[5];
    const float* bk = (const float*)d_in[6];
    const float* wv = (const float*)d_in[7];
    const float* bv = (const float*)d_in[8];
    const float* wo = (const float*)d_in[9];
    const float* bo = (const float*)d_in[10];
    const float* lg = (const float*)d_in[11];
    const float* lb = (const float*)d_in[12];

    float* out  = (float*)d_out;
    float* attn = out + (long long)B_ * L_ * D_;

    uint8_t *qpk, *kpk, *vpk, *wqpk, *wkpk, *wvpk, *wopk, *qhpk, *khpk, *vTpk, *oapk;
    float *vh, *op;
    cudaGetSymbolAddress((void**)&qpk,  g_qpk);
    cudaGetSymbolAddress((void**)&kpk,  g_kpk);
    cudaGetSymbolAddress((void**)&vpk,  g_vpk);
    cudaGetSymbolAddress((void**)&wqpk, g_wqpk);
    cudaGetSymbolAddress((void**)&wkpk, g_wkpk);
    cudaGetSymbolAddress((void**)&wvpk, g_wvpk);
    cudaGetSymbolAddress((void**)&wopk, g_wopk);
    cudaGetSymbolAddress((void**)&qhpk, g_qhpk);
    cudaGetSymbolAddress((void**)&khpk, g_khpk);
    cudaGetSymbolAddress((void**)&vTpk, g_vTpk);
    cudaGetSymbolAddress((void**)&oapk, g_oapk);
    cudaGetSymbolAddress((void**)&vh,   g_vh);
    cudaGetSymbolAddress((void**)&op,   g_op);

    const int SMEMB = 2 * 24576 + 1024;
    const int SMEMF = 163840 + 1024;
    cudaFuncSetAttribute((const void*)pk_gemm<0>, cudaFuncAttributeMaxDynamicSharedMemorySize, SMEMB);
    cudaFuncSetAttribute((const void*)pk_gemm<1>, cudaFuncAttributeMaxDynamicSharedMemorySize, SMEMB);
    cudaFuncSetAttribute((const void*)fused_attn, cudaFuncAttributeMaxDynamicSharedMemorySize, SMEMF);

    dim3 blk(256);

    // pack inputs + weights
    pack_split<<<MROWS_ * D_ / 4 / 256, blk>>>(q, qpk, D_);
    pack_split<<<MROWS_ * D_ / 4 / 256, blk>>>(k, kpk, D_);
    pack_split<<<MROWS_ * D_ / 4 / 256, blk>>>(v, vpk, D_);
    pack_split<<<HD_ * D_ / 4 / 256, blk>>>(wq, wqpk, D_);
    pack_split<<<HD_ * D_ / 4 / 256, blk>>>(wk, wkpk, D_);
    pack_split<<<HD_ * D_ / 4 / 256, blk>>>(wv, wvpk, D_);
    pack_split<<<D_ * HD_ / 4 / 256, blk>>>(wo, wopk, HD_);

    const long long ld32 = 32 * 128;   // 4096B: K=1024 packed row

    // QKV projections (K=1024 -> 32 chunks)
    dim3 gproj(HD_ / 64, MROWS_ / 128, 1);
    pk_gemm<1><<<gproj, blk, SMEMB>>>(qpk, wqpk, bq, nullptr, qhpk, 32, ld32, ld32, 0, ld32);
    pk_gemm<1><<<gproj, blk, SMEMB>>>(kpk, wkpk, bk, nullptr, khpk, 32, ld32, ld32, 0, ld32);
    pk_gemm<0><<<gproj, blk, SMEMB>>>(vpk, wvpk, bv, vh, nullptr, 32, ld32, ld32, HD_, 0);

    transpose_v_pk<<<dim3(L_ / 32, DK_ / 32, B_ * H_), blk>>>(vh, vTpk);

    // Fused attention: writes normalized attn (fp32) + oa packed
    fused_attn<<<dim3(B_ * H_, L_ / 128, 1), blk, SMEMF>>>(qhpk, khpk, vTpk, attn, oapk);

    // Output projection (K=1024 -> 32 chunks)
    dim3 gop(D_ / 64, MROWS_ / 128, 1);
    pk_gemm<0><<<gop, blk, SMEMB>>>(oapk, wopk, bo, op, nullptr, 32, ld32, ld32, D_, 0);

    // LayerNorm + residual
    ln_residual<<<MROWS_, blk>>>(op, q, lg, lb, out);
}

// round 7
// speedup vs baseline: 1.0508x; 1.0508x over previous
#include <cuda_runtime.h>
#include <cuda_bf16.h>
#include <stdint.h>

#define B_   4
#define L_   2048
#define D_   1024
#define H_   16
#define DK_  64
#define HD_  1024
#define MROWS_ 8192
#define LN_EPS_ 1e-5f
#define NROWS_ATTN (B_ * H_ * L_)

// ---------------------------------------------------------------------------
// Scratch (device globals). Packed split-bf16: [M][K/32][32 hi | 32 lo] 128B.
// ---------------------------------------------------------------------------
__device__ __align__(256) uint8_t g_qpk [(long long)MROWS_ * D_ * 4];
__device__ __align__(256) uint8_t g_kpk [(long long)MROWS_ * D_ * 4];
__device__ __align__(256) uint8_t g_vpk [(long long)MROWS_ * D_ * 4];
__device__ __align__(256) uint8_t g_wqpk[(long long)HD_ * D_ * 4];
__device__ __align__(256) uint8_t g_wkpk[(long long)HD_ * D_ * 4];
__device__ __align__(256) uint8_t g_wvpk[(long long)HD_ * D_ * 4];
__device__ __align__(256) uint8_t g_wopk[(long long)D_ * HD_ * 4];
__device__ __align__(256) uint8_t g_qhpk[(long long)MROWS_ * HD_ * 4];
__device__ __align__(256) uint8_t g_khpk[(long long)MROWS_ * HD_ * 4];
__device__ __align__(256) uint8_t g_vTpk[(long long)B_ * H_ * DK_ * L_ * 4];
__device__ __align__(256) uint8_t g_oapk[(long long)MROWS_ * HD_ * 4];
__device__ float g_vh[MROWS_ * HD_];
__device__ float g_op[MROWS_ * HD_];
__device__ float g_rs[NROWS_ATTN];

// ---------------------------------------------------------------------------
// helpers
// ---------------------------------------------------------------------------
__device__ __forceinline__ uint32_t smem_u32(const void* p) {
    uint32_t a;
    asm("{ .reg .u64 t; cvta.to.shared.u64 t, %1; cvt.u32.u64 %0, t; }" : "=r"(a) : "l"(p));
    return a;
}
__device__ __forceinline__ uint32_t sw128(uint32_t off) {
    return off ^ ((off >> 3) & 0x70);
}
__device__ __forceinline__ void cpa16(uint32_t dst, const void* src) {
    asm volatile("cp.async.cg.shared.global [%0], [%1], 16;" :: "r"(dst), "l"(src));
}
#define CP_COMMIT() asm volatile("cp.async.commit_group;" ::: "memory")
#define CP_WAIT0()  asm volatile("cp.async.wait_group 0;" ::: "memory")
#define CP_WAIT1()  asm volatile("cp.async.wait_group 1;" ::: "memory")
#define LDSM_X4(r0, r1, r2, r3, addr)                                      \
    asm volatile("ldmatrix.sync.aligned.m8n8.x4.shared.b16 "               \
                 "{%0,%1,%2,%3}, [%4];"                                    \
                 : "=r"(r0), "=r"(r1), "=r"(r2), "=r"(r3) : "r"(addr))

__device__ __forceinline__ void mma16816(float* d, const uint32_t* a, const uint32_t* b) {
    asm volatile(
        "mma.sync.aligned.m16n8k16.row.col.f32.bf16.bf16.f32 "
        "{%0,%1,%2,%3}, {%4,%5,%6,%7}, {%8,%9}, {%0,%1,%2,%3};"
        : "+f"(d[0]), "+f"(d[1]), "+f"(d[2]), "+f"(d[3])
        : "r"(a[0]), "r"(a[1]), "r"(a[2]), "r"(a[3]), "r"(b[0]), "r"(b[1]));
}

__device__ __forceinline__ void pack_store2(uint8_t* p, float v0, float v1) {
    __nv_bfloat162 h = __floats2bfloat162_rn(v0, v1);
    float2 f = __bfloat1622float2(h);
    __nv_bfloat162 l = __floats2bfloat162_rn(v0 - f.x, v1 - f.y);
    *(uint32_t*)p = *(uint32_t*)&h;
    *(uint32_t*)(p + 64) = *(uint32_t*)&l;
}
__device__ __forceinline__ void pack_store4(uint8_t* p, float4 v) {
    __nv_bfloat162 h0 = __floats2bfloat162_rn(v.x, v.y);
    __nv_bfloat162 h1 = __floats2bfloat162_rn(v.z, v.w);
    float2 f0 = __bfloat1622float2(h0), f1 = __bfloat1622float2(h1);
    __nv_bfloat162 l0 = __floats2bfloat162_rn(v.x - f0.x, v.y - f0.y);
    __nv_bfloat162 l1 = __floats2bfloat162_rn(v.z - f1.x, v.w - f1.y);
    uint2 hu, lu;
    hu.x = *(uint32_t*)&h0; hu.y = *(uint32_t*)&h1;
    lu.x = *(uint32_t*)&l0; lu.y = *(uint32_t*)&l1;
    *(uint2*)p = hu;
    *(uint2*)(p + 64) = lu;
}
__device__ __forceinline__ void combine8(const uint4 h, const uint4 l, float inv, float* out) {
    const uint32_t hu[4] = { h.x, h.y, h.z, h.w };
    const uint32_t lu[4] = { l.x, l.y, l.z, l.w };
#pragma unroll
    for (int j = 0; j < 4; j++) {
        __nv_bfloat162 hb = *(const __nv_bfloat162*)&hu[j];
        __nv_bfloat162 lb = *(const __nv_bfloat162*)&lu[j];
        float2 hf = __bfloat1622float2(hb), lf = __bfloat1622float2(lb);
        out[2 * j]     = (hf.x + lf.x) * inv;
        out[2 * j + 1] = (hf.y + lf.y) * inv;
    }
}

// ---------------------------------------------------------------------------
// pack fp32 [M,K] -> packed split bf16 ; batched over 3 tensors via blockIdx.z
// ---------------------------------------------------------------------------
__global__ void __launch_bounds__(256)
pack_split3(const float* __restrict__ s0, const float* __restrict__ s1,
            const float* __restrict__ s2,
            uint8_t* __restrict__ d0, uint8_t* __restrict__ d1,
            uint8_t* __restrict__ d2, int K)
{
    const float* src = (blockIdx.z == 0) ? s0 : (blockIdx.z == 1) ? s1 : s2;
    uint8_t* dst = (blockIdx.z == 0) ? d0 : (blockIdx.z == 1) ? d1 : d2;
    const long long idx = (long long)blockIdx.x * 256 + threadIdx.x;
    const int perRow = K >> 2;
    const long long m = idx / perRow;
    const int j = (int)(idx - m * perRow);
    float4 v = *(const float4*)(src + m * K + j * 4);
    const int e0 = j * 4;
    uint8_t* p = dst + (m * (K >> 5) + (e0 >> 5)) * 128 + (e0 & 31) * 2;
    pack_store4(p, v);
}
__global__ void __launch_bounds__(256)
pack_split1(const float* __restrict__ src, uint8_t* __restrict__ dst, int K)
{
    const long long idx = (long long)blockIdx.x * 256 + threadIdx.x;
    const int perRow = K >> 2;
    const long long m = idx / perRow;
    const int j = (int)(idx - m * perRow);
    float4 v = *(const float4*)(src + m * K + j * 4);
    const int e0 = j * 4;
    uint8_t* p = dst + (m * (K >> 5) + (e0 >> 5)) * 128 + (e0 & 31) * 2;
    pack_store4(p, v);
}

// ---------------------------------------------------------------------------
// Packed split-bf16 GEMM. 128x64 tile, K-stage=64 (2 chunks), 8 warps, 2 CTA/SM.
// MODE 0: C fp32 + bias.  MODE 1: C packed + bias.
// MODE 2: exp(alpha*acc) -> packed + rowsum atomics.
// MODE 3: A staged tiles -> normalized fp32 P write; epilogue *1/rowsum -> packed.
// nstages = K/64.  ldA/ldB = row strides in bytes.
// ---------------------------------------------------------------------------
template<int MODE>
__global__ void __launch_bounds__(256, 2)
pk_gemm(const uint8_t* Apk, const uint8_t* __restrict__ Bpk,
        const float* __restrict__ bias,
        float* Cf, uint8_t* Cpk, float* rs,
        int nstages, long long ldA, long long ldB, int ldc, long long ldCpk,
        int zdiv,
        long long sAo, long long sAi, long long sBo, long long sBi,
        long long sCfO, long long sCfI, long long sCpO, long long sCpI,
        long long rsO, long long rsI, float alpha)
{
    extern __shared__ uint8_t dyn_raw[];
    __shared__ float s_bias[64];
    __shared__ float s_aux[128];

    const int tid = threadIdx.x, wid = tid >> 5, lane = tid & 31;
    const int z = blockIdx.z, zo = z / zdiv, zi = z - zo * zdiv;
    Apk += zo * sAo + zi * sAi;
    Bpk += zo * sBo + zi * sBi;
    if (MODE == 0 || MODE == 3) Cf += zo * sCfO + zi * sCfI;
    if (MODE == 1 || MODE == 2 || MODE == 3) Cpk += zo * sCpO + zi * sCpI;
    const long long rs_off = zo * rsO + zi * rsI;

    const long long m0 = (long long)blockIdx.y * 128;
    const long long n0 = (long long)blockIdx.x * 64;

    uint32_t raw = smem_u32(dyn_raw);
    uint32_t base = (raw + 1023u) & ~1023u;
    uint8_t* dsm = dyn_raw + (base - raw);
    // stage: A 32KB (2x16KB chunks) + B 16KB (2x8KB) = 48KB
    uint8_t* smA[2] = { dsm, dsm + 49152 };
    const uint32_t aSu[2] = { base, base + 49152 };
    const uint32_t bSu[2] = { base + 32768, base + 49152 + 32768 };

    if (MODE == 0 || MODE == 1) { if (tid < 64) s_bias[tid] = bias ? bias[n0 + tid] : 0.0f; }
    if (MODE == 2) { if (tid < 128) s_aux[tid] = 0.0f; }
    if (MODE == 3) { if (tid < 128) s_aux[tid] = 1.0f / rs[rs_off + m0 + tid]; }

    float acc[4][2][4];
#pragma unroll
    for (int i = 0; i < 4; i++)
#pragma unroll
        for (int j = 0; j < 2; j++)
#pragma unroll
            for (int e = 0; e < 4; e++) acc[i][j][e] = 0.0f;

    const uint32_t a_row = (uint32_t)((lane & 7) + (lane & 8));
    const uint32_t a_kof = (uint32_t)(((lane >> 4) & 1) * 16);
    const uint32_t b_row = (uint32_t)((lane & 7) + ((lane >> 4) & 1) * 8);
    const uint32_t b_kof = (uint32_t)(((lane >> 3) & 1) * 16);
    const int wm = (wid & 1) * 64;
    const int wn = (wid >> 1) * 16;

    // one stage = two 32-K chunks (A: 8 cp / chunk pair; B: 4)
    auto prefetch = [&](int s, int c) {
        const uint8_t* Ab = Apk + (long long)c * 256;
#pragma unroll
        for (int half = 0; half < 2; half++) {
#pragma unroll
            for (int i = 0; i < 4; i++) {
                const int idx = i * 256 + tid, row = idx >> 3, g = idx & 7;
                cpa16(aSu[s] + half * 16384 + sw128((uint32_t)(row * 128 + g * 16)),
                      Ab + (m0 + row) * ldA + half * 128 + g * 16);
            }
        }
        const uint8_t* Bb = Bpk + (long long)c * 256;
#pragma unroll
        for (int half = 0; half < 2; half++) {
#pragma unroll
            for (int i = 0; i < 2; i++) {
                const int idx = i * 256 + tid, row = idx >> 3, g = idx & 7;
                cpa16(bSu[s] + half * 8192 + sw128((uint32_t)(row * 128 + g * 16)),
                      Bb + (n0 + row) * ldB + half * 128 + g * 16);
            }
        }
        CP_COMMIT();
    };

    prefetch(0, 0);
    int cur = 0;
    for (int c = 0; c < nstages; c++) {
        if (c + 1 < nstages) {
            prefetch(cur ^ 1, c + 1);
            CP_WAIT1();
        } else {
            CP_WAIT0();
        }
        __syncthreads();

        if (MODE == 3) {
            // reconstruct normalized fp32 P for this 64-K stage (in place)
            const int r = tid >> 1, hh = tid & 1;
            const uint8_t* sa = smA[cur];
            const float inv = s_aux[r];
#pragma unroll
            for (int half = 0; half < 2; half++) {
                const uint8_t* sab = sa + half * 16384;
                uint4 h0 = *(const uint4*)(sab + sw128((uint32_t)(r * 128 + hh * 32)));
                uint4 h1 = *(const uint4*)(sab + sw128((uint32_t)(r * 128 + hh * 32 + 16)));
                uint4 l0 = *(const uint4*)(sab + sw128((uint32_t)(r * 128 + 64 + hh * 32)));
                uint4 l1 = *(const uint4*)(sab + sw128((uint32_t)(r * 128 + 64 + hh * 32 + 16)));
                float o[16];
                combine8(h0, l0, inv, o);
                combine8(h1, l1, inv, o + 8);
                float* dst = Cf + (m0 + r) * (long long)ldc + c * 64 + half * 32 + hh * 16;
                *(float4*)(dst +  0) = make_float4(o[0],  o[1],  o[2],  o[3]);
                *(float4*)(dst +  4) = make_float4(o[4],  o[5],  o[6],  o[7]);
                *(float4*)(dst +  8) = make_float4(o[8],  o[9],  o[10], o[11]);
                *(float4*)(dst + 12) = make_float4(o[12], o[13], o[14], o[15]);
            }
        }

#pragma unroll
        for (int half = 0; half < 2; half++) {
            const uint32_t aS = aSu[cur] + half * 16384;
            const uint32_t bS = bSu[cur] + half * 8192;
#pragma unroll
            for (int ks = 0; ks < 2; ks++) {
                uint32_t ah[4][4], al[4][4], bh[2][2], bl[2][2];
#pragma unroll
                for (int mt = 0; mt < 4; mt++) {
                    uint32_t off = (uint32_t)(wm + mt * 16 + a_row) * 128 + ks * 32 + a_kof;
                    LDSM_X4(ah[mt][0], ah[mt][1], ah[mt][2], ah[mt][3], aS + sw128(off));
                }
                {
                    uint32_t r0, r1, r2, r3;
                    uint32_t off = (uint32_t)(wn + b_row) * 128 + ks * 32 + b_kof;
                    LDSM_X4(r0, r1, r2, r3, bS + sw128(off));
                    bh[0][0] = r0; bh[0][1] = r1; bh[1][0] = r2; bh[1][1] = r3;
                }
#pragma unroll
                for (int mt = 0; mt < 4; mt++)
#pragma unroll
                    for (int nt = 0; nt < 2; nt++)
                        mma16816(acc[mt][nt], ah[mt], bh[nt]);
                {
                    uint32_t r0, r1, r2, r3;
                    uint32_t off = (uint32_t)(wn + b_row) * 128 + 64 + ks * 32 + b_kof;
                    LDSM_X4(r0, r1, r2, r3, bS + sw128(off));
                    bl[0][0] = r0; bl[0][1] = r1; bl[1][0] = r2; bl[1][1] = r3;
                }
#pragma unroll
                for (int mt = 0; mt < 4; mt++)
#pragma unroll
                    for (int nt = 0; nt < 2; nt++)
                        mma16816(acc[mt][nt], ah[mt], bl[nt]);
#pragma unroll
                for (int mt = 0; mt < 4; mt++) {
                    uint32_t off = (uint32_t)(wm + mt * 16 + a_row) * 128 + 64 + ks * 32 + a_kof;
                    LDSM_X4(al[mt][0], al[mt][1], al[mt][2], al[mt][3], aS + sw128(off));
                }
#pragma unroll
                for (int mt = 0; mt < 4; mt++)
#pragma unroll
                    for (int nt = 0; nt < 2; nt++)
                        mma16816(acc[mt][nt], al[mt], bh[nt]);
            }
        }
        __syncthreads();
        cur ^= 1;
    }

    // ---- epilogue ----
    const int g = lane >> 2, t = lane & 3;
    if (MODE == 2) {
#pragma unroll
        for (int mt = 0; mt < 4; mt++) {
            float sum0 = 0.0f, sum1 = 0.0f;
#pragma unroll
            for (int nt = 0; nt < 2; nt++) {
                const int colw = wn + nt * 8 + 2 * t;
                const long long row0 = m0 + wm + mt * 16 + g;
                float e0 = __expf(acc[mt][nt][0] * alpha);
                float e1 = __expf(acc[mt][nt][1] * alpha);
                float e2 = __expf(acc[mt][nt][2] * alpha);
                float e3 = __expf(acc[mt][nt][3] * alpha);
                const long long colg = n0 + colw;
                const long long ch = colg >> 5;
                const int wi = (int)(colg & 31);
                pack_store2(Cpk + row0 * ldCpk + ch * 128 + wi * 2, e0, e1);
                pack_store2(Cpk + (row0 + 8) * ldCpk + ch * 128 + wi * 2, e2, e3);
                sum0 += e0 + e1; sum1 += e2 + e3;
            }
            sum0 += __shfl_xor_sync(0xffffffffu, sum0, 1);
            sum0 += __shfl_xor_sync(0xffffffffu, sum0, 2);
            sum1 += __shfl_xor_sync(0xffffffffu, sum1, 1);
            sum1 += __shfl_xor_sync(0xffffffffu, sum1, 2);
            if (t == 0) {
                atomicAdd(&s_aux[wm + mt * 16 + g], sum0);
                atomicAdd(&s_aux[wm + mt * 16 + g + 8], sum1);
            }
        }
        __syncthreads();
        if (tid < 128)
            atomicAdd(&rs[rs_off + m0 + tid], s_aux[tid]);
    } else if (MODE == 1 || MODE == 3) {
#pragma unroll
        for (int mt = 0; mt < 4; mt++) {
            const float i0 = (MODE == 3) ? s_aux[wm + mt * 16 + g] : 1.0f;
            const float i1 = (MODE == 3) ? s_aux[wm + mt * 16 + g + 8] : 1.0f;
#pragma unroll
            for (int nt = 0; nt < 2; nt++) {
                const int colw = wn + nt * 8 + 2 * t;
                const long long row0 = m0 + wm + mt * 16 + g;
                const float b0 = (MODE == 1) ? s_bias[colw] : 0.0f;
                const float b1 = (MODE == 1) ? s_bias[colw + 1] : 0.0f;
                float v0 = acc[mt][nt][0] * i0 + b0;
                float v1 = acc[mt][nt][1] * i0 + b1;
                float v2 = acc[mt][nt][2] * i1 + b0;
                float v3 = acc[mt][nt][3] * i1 + b1;
                const long long colg = n0 + colw;
                const long long ch = colg >> 5;
                const int wi = (int)(colg & 31);
                pack_store2(Cpk + row0 * ldCpk + ch * 128 + wi * 2, v0, v1);
                pack_store2(Cpk + (row0 + 8) * ldCpk + ch * 128 + wi * 2, v2, v3);
            }
        }
    } else {
#pragma unroll
        for (int mt = 0; mt < 4; mt++) {
#pragma unroll
            for (int nt = 0; nt < 2; nt++) {
                const int colw = wn + nt * 8 + 2 * t;
                const float b0 = s_bias[colw], b1 = s_bias[colw + 1];
                const long long row0 = m0 + wm + mt * 16 + g;
                *(float2*)(Cf + row0 * (long long)ldc + n0 + colw) =
                    make_float2(acc[mt][nt][0] + b0, acc[mt][nt][1] + b1);
                *(float2*)(Cf + (row0 + 8) * (long long)ldc + n0 + colw) =
                    make_float2(acc[mt][nt][2] + b0, acc[mt][nt][3] + b1);
            }
        }
    }
}

// ---------------------------------------------------------------------------
// V transpose: vh fp32 [B,L,H,DK] -> vT packed [(b*H+h)][dk][L/32][128B]
// ---------------------------------------------------------------------------
__global__ void __launch_bounds__(256)
transpose_v_pk(const float* __restrict__ vh, uint8_t* __restrict__ vT)
{
    __shared__ float tsm[32][33];
    const int bh = blockIdx.z;
    const int b = bh >> 4, h = bh & 15;
    const int l0 = blockIdx.x * 32;
    const int d0 = blockIdx.y * 32;
    const int tid = threadIdx.x;
    const int tx = tid & 31;
    const int ty = tid >> 5;

    const float* src = vh + ((long long)b * L_ + l0) * HD_ + h * DK_ + d0;
#pragma unroll
    for (int i = 0; i < 32; i += 8)
        tsm[ty + i][tx] = src[(long long)(ty + i) * HD_ + tx];
    __syncthreads();

    const int lp = tid & 15;
#pragma unroll
    for (int it = 0; it < 2; it++) {
        const int d = (tid >> 4) + 16 * it;
        uint8_t* p = vT + ((long long)bh * 64 + d0 + d) * (L_ / 32 * 128)
                        + (l0 >> 5) * 128 + lp * 4;
        pack_store2(p, tsm[2 * lp][d], tsm[2 * lp + 1][d]);
    }
}

__global__ void zero_rs(float* __restrict__ rs)
{
    rs[blockIdx.x * 256 + threadIdx.x] = 0.0f;
}

// ---------------------------------------------------------------------------
// LayerNorm + residual
// ---------------------------------------------------------------------------
__global__ void __launch_bounds__(256)
ln_residual(const float* __restrict__ x, const float* __restrict__ res,
            const float* __restrict__ gam, const float* __restrict__ bet,
            float* __restrict__ out)
{
    const long long row = blockIdx.x;
    const float4* x4 = (const float4*)(x   + row * D_);
    const float4* r4 = (const float4*)(res + row * D_);
    const int tid = threadIdx.x;

    float4 v = x4[tid];
    float s  = (v.x + v.y) + (v.z + v.w);
    float sq = (v.x * v.x + v.y * v.y) + (v.z * v.z + v.w * v.w);
#pragma unroll
    for (int o = 16; o > 0; o >>= 1) {
        s  += __shfl_xor_sync(0xffffffffu, s,  o);
        sq += __shfl_xor_sync(0xffffffffu, sq, o);
    }
    __shared__ float ss[8], sqs[8];
    if ((tid & 31) == 0) { ss[tid >> 5] = s; sqs[tid >> 5] = sq; }
    __syncthreads();
    s  = (ss[0]  + ss[1])  + (ss[2]  + ss[3])  + (ss[4]  + ss[5])  + (ss[6]  + ss[7]);
    sq = (sqs[0] + sqs[1]) + (sqs[2] + sqs[3]) + (sqs[4] + sqs[5]) + (sqs[6] + sqs[7]);

    const float mean = s * (1.0f / D_);
    float var = sq * (1.0f / D_) - mean * mean;
    var = fmaxf(var, 0.0f);
    const float rstd = rsqrtf(var + LN_EPS_);

    float4 g  = ((const float4*)gam)[tid];
    float4 bt = ((const float4*)bet)[tid];
    float4 r  = r4[tid];
    float4 o;
    o.x = (v.x - mean) * rstd * g.x + bt.x + r.x;
    o.y = (v.y - mean) * rstd * g.y + bt.y + r.y;
    o.z = (v.z - mean) * rstd * g.z + bt.z + r.z;
    o.w = (v.w - mean) * rstd * g.w + bt.w + r.w;
    ((float4*)(out + row * D_))[tid] = o;
}

// ---------------------------------------------------------------------------
// Launch
// ---------------------------------------------------------------------------
extern "C" void kernel_launch(void* const* d_in, const int* in_sizes, int n_in,
                              void* d_out, int out_size)
{
    (void)in_sizes; (void)n_in; (void)out_size;
    const float* q  = (const float*)d_in[0];
    const float* k  = (const float*)d_in[1];
    const float* v  = (const float*)d_in[2];
    const float* wq = (const float*)d_in[3];
    const float* bq = (const float*)d_in[4];
    const float* wk = (const float*)d_in[5];
    const float* bk = (const float*)d_in[6];
    const float* wv = (const float*)d_in[7];
    const float* bv = (const float*)d_in[8];
    const float* wo = (const float*)d_in[9];
    const float* bo = (const float*)d_in[10];
    const float* lg = (const float*)d_in[11];
    const float* lb = (const float*)d_in[12];

    float* out  = (float*)d_out;
    float* attn = out + (long long)B_ * L_ * D_;
    uint8_t* attn_b = (uint8_t*)attn;

    uint8_t *qpk, *kpk, *vpk, *wqpk, *wkpk, *wvpk, *wopk, *qhpk, *khpk, *vTpk, *oapk;
    float *vh, *op, *rs;
    cudaGetSymbolAddress((void**)&qpk,  g_qpk);
    cudaGetSymbolAddress((void**)&kpk,  g_kpk);
    cudaGetSymbolAddress((void**)&vpk,  g_vpk);
    cudaGetSymbolAddress((void**)&wqpk, g_wqpk);
    cudaGetSymbolAddress((void**)&wkpk, g_wkpk);
    cudaGetSymbolAddress((void**)&wvpk, g_wvpk);
    cudaGetSymbolAddress((void**)&wopk, g_wopk);
    cudaGetSymbolAddress((void**)&qhpk, g_qhpk);
    cudaGetSymbolAddress((void**)&khpk, g_khpk);
    cudaGetSymbolAddress((void**)&vTpk, g_vTpk);
    cudaGetSymbolAddress((void**)&oapk, g_oapk);
    cudaGetSymbolAddress((void**)&vh,   g_vh);
    cudaGetSymbolAddress((void**)&op,   g_op);
    cudaGetSymbolAddress((void**)&rs,   g_rs);

    const int SMEMB = 2 * 49152 + 1024;   // 99328
    cudaFuncSetAttribute((const void*)pk_gemm<0>, cudaFuncAttributeMaxDynamicSharedMemorySize, SMEMB);
    cudaFuncSetAttribute((const void*)pk_gemm<1>, cudaFuncAttributeMaxDynamicSharedMemorySize, SMEMB);
    cudaFuncSetAttribute((const void*)pk_gemm<2>, cudaFuncAttributeMaxDynamicSharedMemorySize, SMEMB);
    cudaFuncSetAttribute((const void*)pk_gemm<3>, cudaFuncAttributeMaxDynamicSharedMemorySize, SMEMB);

    dim3 blk(256);

    zero_rs<<<NROWS_ATTN / 256, blk>>>(rs);

    // pack inputs + weights (batched)
    pack_split3<<<dim3(MROWS_ * D_ / 4 / 256, 1, 3), blk>>>(q, k, v, qpk, kpk, vpk, D_);
    pack_split3<<<dim3(HD_ * D_ / 4 / 256, 1, 3), blk>>>(wq, wk, wv, wqpk, wkpk, wvpk, D_);
    pack_split1<<<D_ * HD_ / 4 / 256, blk>>>(wo, wopk, HD_);

    const long long ld32 = 32 * 128;   // 4096B row (K=1024)
    const long long ld64 = 64 * 128;   // 8192B row (K=2048)

    // QKV projections (K=1024 -> 16 stages)
    dim3 gproj(HD_ / 64, MROWS_ / 128, 1);
    pk_gemm<1><<<gproj, blk, SMEMB>>>(qpk, wqpk, bq, nullptr, qhpk, nullptr,
        16, ld32, ld32, 0, ld32, 1,
        0, 0, 0, 0, 0, 0, 0, 0, 0, 0, 1.0f);
    pk_gemm<1><<<gproj, blk, SMEMB>>>(kpk, wkpk, bk, nullptr, khpk, nullptr,
        16, ld32, ld32, 0, ld32, 1,
        0, 0, 0, 0, 0, 0, 0, 0, 0, 0, 1.0f);
    pk_gemm<0><<<gproj, blk, SMEMB>>>(vpk, wvpk, bv, vh, nullptr, nullptr,
        16, ld32, ld32, HD_, 0, 1,
        0, 0, 0, 0, 0, 0, 0, 0, 0, 0, 1.0f);

    transpose_v_pk<<<dim3(L_ / 32, DK_ / 32, B_ * H_), blk>>>(vh, vTpk);

    // Scores (K=64 -> 1 stage): attn[(h*B+b)] = exp((qh@kh^T)/8) packed + rowsums
    dim3 gsc(L_ / 64, L_ / 128, B_ * H_);
    pk_gemm<2><<<gsc, blk, SMEMB>>>(qhpk, khpk, nullptr, nullptr, attn_b, rs,
        1, ld32, ld32, 0, ld64, H_,
        (long long)L_ * ld32, 256,
        (long long)L_ * ld32, 256,
        0, 0,
        (long long)L_ * L_ * 4, (long long)B_ * L_ * L_ * 4,
        (long long)L_, (long long)B_ * L_,
        0.125f);

    // PV (K=2048 -> 32 stages): in-place normalized P + oa packed
    dim3 gpv(1, L_ / 128, B_ * H_);
    pk_gemm<3><<<gpv, blk, SMEMB>>>(attn_b, vTpk, nullptr, attn, oapk, rs,
        32, ld64, ld64, L_, ld32, H_,
        (long long)L_ * L_ * 4, (long long)B_ * L_ * L_ * 4,
        (long long)DK_ * ld64 * H_, (long long)DK_ * ld64,
        (long long)L_ * L_, (long long)B_ * L_ * L_,
        (long long)L_ * ld32, 256,
        (long long)L_, (long long)B_ * L_,
        1.0f);

    // Output projection (K=1024 -> 16 stages)
    dim3 gop(D_ / 64, MROWS_ / 128, 1);
    pk_gemm<0><<<gop, blk, SMEMB>>>(oapk, wopk, bo, op, nullptr, nullptr,
        16, ld32, ld32, D_, 0, 1,
        0, 0, 0, 0, 0, 0, 0, 0, 0, 0, 1.0f);

    // LayerNorm + residual
    ln_residual<<<MROWS_, blk>>>(op, q, lg, lb, out);
}

// round 8
// speedup vs baseline: 1.0803x; 1.0281x over previous
#include <cuda_runtime.h>
#include <cuda_bf16.h>
#include <stdint.h>

#define B_   4
#define L_   2048
#define D_   1024
#define H_   16
#define DK_  64
#define HD_  1024
#define MROWS_ 8192
#define LN_EPS_ 1e-5f
#define NROWS_ATTN (B_ * H_ * L_)

// ---------------------------------------------------------------------------
// Scratch (device globals). Packed split-bf16: [M][K/32][32 hi | 32 lo] 128B.
// ---------------------------------------------------------------------------
__device__ __align__(256) uint8_t g_qpk [(long long)MROWS_ * D_ * 4];
__device__ __align__(256) uint8_t g_kpk [(long long)MROWS_ * D_ * 4];
__device__ __align__(256) uint8_t g_vpk [(long long)MROWS_ * D_ * 4];
__device__ __align__(256) uint8_t g_wqpk[(long long)HD_ * D_ * 4];
__device__ __align__(256) uint8_t g_wkpk[(long long)HD_ * D_ * 4];
__device__ __align__(256) uint8_t g_wvpk[(long long)HD_ * D_ * 4];
__device__ __align__(256) uint8_t g_wopk[(long long)D_ * HD_ * 4];
__device__ __align__(256) uint8_t g_qhpk[(long long)MROWS_ * HD_ * 4];
__device__ __align__(256) uint8_t g_khpk[(long long)MROWS_ * HD_ * 4];
__device__ __align__(256) uint8_t g_vTpk[(long long)B_ * H_ * DK_ * L_ * 4];
__device__ __align__(256) uint8_t g_oapk[(long long)MROWS_ * HD_ * 4];
__device__ float g_vh[MROWS_ * HD_];
__device__ float g_op[MROWS_ * HD_];
__device__ float g_rs[NROWS_ATTN];

// ---------------------------------------------------------------------------
// helpers
// ---------------------------------------------------------------------------
__device__ __forceinline__ uint32_t smem_u32(const void* p) {
    uint32_t a;
    asm("{ .reg .u64 t; cvta.to.shared.u64 t, %1; cvt.u32.u64 %0, t; }" : "=r"(a) : "l"(p));
    return a;
}
__device__ __forceinline__ uint32_t sw128(uint32_t off) {
    return off ^ ((off >> 3) & 0x70);
}
__device__ __forceinline__ void cpa16(uint32_t dst, const void* src) {
    asm volatile("cp.async.cg.shared.global [%0], [%1], 16;" :: "r"(dst), "l"(src));
}
#define CP_COMMIT() asm volatile("cp.async.commit_group;" ::: "memory")
#define CP_WAIT0()  asm volatile("cp.async.wait_group 0;" ::: "memory")
#define CP_WAIT1()  asm volatile("cp.async.wait_group 1;" ::: "memory")
#define LDSM_X4(r0, r1, r2, r3, addr)                                      \
    asm volatile("ldmatrix.sync.aligned.m8n8.x4.shared.b16 "               \
                 "{%0,%1,%2,%3}, [%4];"                                    \
                 : "=r"(r0), "=r"(r1), "=r"(r2), "=r"(r3) : "r"(addr))

__device__ __forceinline__ void mma16816(float* d, const uint32_t* a, const uint32_t* b) {
    asm volatile(
        "mma.sync.aligned.m16n8k16.row.col.f32.bf16.bf16.f32 "
        "{%0,%1,%2,%3}, {%4,%5,%6,%7}, {%8,%9}, {%0,%1,%2,%3};"
        : "+f"(d[0]), "+f"(d[1]), "+f"(d[2]), "+f"(d[3])
        : "r"(a[0]), "r"(a[1]), "r"(a[2]), "r"(a[3]), "r"(b[0]), "r"(b[1]));
}

__device__ __forceinline__ void pack_store2(uint8_t* p, float v0, float v1) {
    __nv_bfloat162 h = __floats2bfloat162_rn(v0, v1);
    float2 f = __bfloat1622float2(h);
    __nv_bfloat162 l = __floats2bfloat162_rn(v0 - f.x, v1 - f.y);
    *(uint32_t*)p = *(uint32_t*)&h;
    *(uint32_t*)(p + 64) = *(uint32_t*)&l;
}
__device__ __forceinline__ void pack_store4(uint8_t* p, float4 v) {
    __nv_bfloat162 h0 = __floats2bfloat162_rn(v.x, v.y);
    __nv_bfloat162 h1 = __floats2bfloat162_rn(v.z, v.w);
    float2 f0 = __bfloat1622float2(h0), f1 = __bfloat1622float2(h1);
    __nv_bfloat162 l0 = __floats2bfloat162_rn(v.x - f0.x, v.y - f0.y);
    __nv_bfloat162 l1 = __floats2bfloat162_rn(v.z - f1.x, v.w - f1.y);
    uint2 hu, lu;
    hu.x = *(uint32_t*)&h0; hu.y = *(uint32_t*)&h1;
    lu.x = *(uint32_t*)&l0; lu.y = *(uint32_t*)&l1;
    *(uint2*)p = hu;
    *(uint2*)(p + 64) = lu;
}
__device__ __forceinline__ void combine8(const uint4 h, const uint4 l, float inv, float* out) {
    const uint32_t hu[4] = { h.x, h.y, h.z, h.w };
    const uint32_t lu[4] = { l.x, l.y, l.z, l.w };
#pragma unroll
    for (int j = 0; j < 4; j++) {
        __nv_bfloat162 hb = *(const __nv_bfloat162*)&hu[j];
        __nv_bfloat162 lb = *(const __nv_bfloat162*)&lu[j];
        float2 hf = __bfloat1622float2(hb), lf = __bfloat1622float2(lb);
        out[2 * j]     = (hf.x + lf.x) * inv;
        out[2 * j + 1] = (hf.y + lf.y) * inv;
    }
}

// ---------------------------------------------------------------------------
// pack fp32 [M,K] -> packed split bf16 ; batched over 3 tensors via blockIdx.z
// ---------------------------------------------------------------------------
__global__ void __launch_bounds__(256)
pack_split3(const float* __restrict__ s0, const float* __restrict__ s1,
            const float* __restrict__ s2,
            uint8_t* __restrict__ d0, uint8_t* __restrict__ d1,
            uint8_t* __restrict__ d2, int K)
{
    const float* src = (blockIdx.z == 0) ? s0 : (blockIdx.z == 1) ? s1 : s2;
    uint8_t* dst = (blockIdx.z == 0) ? d0 : (blockIdx.z == 1) ? d1 : d2;
    const long long idx = (long long)blockIdx.x * 256 + threadIdx.x;
    const int perRow = K >> 2;
    const long long m = idx / perRow;
    const int j = (int)(idx - m * perRow);
    float4 v = *(const float4*)(src + m * K + j * 4);
    const int e0 = j * 4;
    uint8_t* p = dst + (m * (K >> 5) + (e0 >> 5)) * 128 + (e0 & 31) * 2;
    pack_store4(p, v);
}
__global__ void __launch_bounds__(256)
pack_split1(const float* __restrict__ src, uint8_t* __restrict__ dst, int K)
{
    const long long idx = (long long)blockIdx.x * 256 + threadIdx.x;
    const int perRow = K >> 2;
    const long long m = idx / perRow;
    const int j = (int)(idx - m * perRow);
    float4 v = *(const float4*)(src + m * K + j * 4);
    const int e0 = j * 4;
    uint8_t* p = dst + (m * (K >> 5) + (e0 >> 5)) * 128 + (e0 & 31) * 2;
    pack_store4(p, v);
}

// ---------------------------------------------------------------------------
// Packed split-bf16 GEMM. 128x64 tile, 32-K chunks, 8 warps as 4x2 (warp tile
// 32x32 => A-tile read by only 2 warp-columns), 2 CTAs/SM.
// MODE 0: C fp32 + bias.  MODE 1: C packed + bias.
// MODE 2: exp(alpha*acc) -> packed + rowsum atomics.
// MODE 3: A staged tiles -> normalized fp32 P write; epilogue *1/rowsum -> packed.
// ---------------------------------------------------------------------------
template<int MODE>
__global__ void __launch_bounds__(256, 2)
pk_gemm(const uint8_t* Apk, const uint8_t* __restrict__ Bpk,
        const float* __restrict__ bias,
        float* Cf, uint8_t* Cpk, float* rs,
        int nchunks, long long ldA, long long ldB, int ldc, long long ldCpk,
        int zdiv,
        long long sAo, long long sAi, long long sBo, long long sBi,
        long long sCfO, long long sCfI, long long sCpO, long long sCpI,
        long long rsO, long long rsI, float alpha)
{
    extern __shared__ uint8_t dyn_raw[];
    __shared__ float s_bias[64];
    __shared__ float s_aux[128];

    const int tid = threadIdx.x, wid = tid >> 5, lane = tid & 31;
    const int z = blockIdx.z, zo = z / zdiv, zi = z - zo * zdiv;
    Apk += zo * sAo + zi * sAi;
    Bpk += zo * sBo + zi * sBi;
    if (MODE == 0 || MODE == 3) Cf += zo * sCfO + zi * sCfI;
    if (MODE == 1 || MODE == 2 || MODE == 3) Cpk += zo * sCpO + zi * sCpI;
    const long long rs_off = zo * rsO + zi * rsI;

    const long long m0 = (long long)blockIdx.y * 128;
    const long long n0 = (long long)blockIdx.x * 64;

    uint32_t raw = smem_u32(dyn_raw);
    uint32_t base = (raw + 1023u) & ~1023u;
    uint8_t* dsm = dyn_raw + (base - raw);
    uint8_t* smA[2] = { dsm, dsm + 24576 };
    const uint32_t aSu[2] = { base, base + 24576 };
    const uint32_t bSu[2] = { base + 16384, base + 24576 + 16384 };

    if (MODE == 0 || MODE == 1) { if (tid < 64) s_bias[tid] = bias ? bias[n0 + tid] : 0.0f; }
    if (MODE == 2) { if (tid < 128) s_aux[tid] = 0.0f; }
    if (MODE == 3) { if (tid < 128) s_aux[tid] = 1.0f / rs[rs_off + m0 + tid]; }

    float acc[2][4][4];
#pragma unroll
    for (int i = 0; i < 2; i++)
#pragma unroll
        for (int j = 0; j < 4; j++)
#pragma unroll
            for (int e = 0; e < 4; e++) acc[i][j][e] = 0.0f;

    const uint32_t a_row = (uint32_t)((lane & 7) + (lane & 8));
    const uint32_t a_kof = (uint32_t)(((lane >> 4) & 1) * 16);
    const uint32_t b_row = (uint32_t)((lane & 7) + ((lane >> 4) & 1) * 8);
    const uint32_t b_kof = (uint32_t)(((lane >> 3) & 1) * 16);
    // 4x2 warp grid: warp tile 32(M) x 32(N)
    const int wm = (wid & 3) * 32;
    const int wn = (wid >> 2) * 32;

    auto prefetch = [&](int s, int c) {
        const uint8_t* Ab = Apk + (long long)c * 128;
#pragma unroll
        for (int i = 0; i < 4; i++) {
            const int idx = i * 256 + tid, row = idx >> 3, g = idx & 7;
            cpa16(aSu[s] + sw128((uint32_t)(row * 128 + g * 16)),
                  Ab + (m0 + row) * ldA + g * 16);
        }
        const uint8_t* Bb = Bpk + (long long)c * 128;
#pragma unroll
        for (int i = 0; i < 2; i++) {
            const int idx = i * 256 + tid, row = idx >> 3, g = idx & 7;
            cpa16(bSu[s] + sw128((uint32_t)(row * 128 + g * 16)),
                  Bb + (n0 + row) * ldB + g * 16);
        }
        CP_COMMIT();
    };

    prefetch(0, 0);
    int cur = 0;
    for (int c = 0; c < nchunks; c++) {
        if (c + 1 < nchunks) {
            prefetch(cur ^ 1, c + 1);
            CP_WAIT1();
        } else {
            CP_WAIT0();
        }
        __syncthreads();

        if (MODE == 3) {
            // reconstruct normalized fp32 P for this 32-K chunk (in place)
            const int r = tid >> 1, hh = tid & 1;
            const uint8_t* sa = smA[cur];
            const float inv = s_aux[r];
            uint4 h0 = *(const uint4*)(sa + sw128((uint32_t)(r * 128 + hh * 32)));
            uint4 h1 = *(const uint4*)(sa + sw128((uint32_t)(r * 128 + hh * 32 + 16)));
            uint4 l0 = *(const uint4*)(sa + sw128((uint32_t)(r * 128 + 64 + hh * 32)));
            uint4 l1 = *(const uint4*)(sa + sw128((uint32_t)(r * 128 + 64 + hh * 32 + 16)));
            float o[16];
            combine8(h0, l0, inv, o);
            combine8(h1, l1, inv, o + 8);
            float* dst = Cf + (m0 + r) * (long long)ldc + c * 32 + hh * 16;
            *(float4*)(dst +  0) = make_float4(o[0],  o[1],  o[2],  o[3]);
            *(float4*)(dst +  4) = make_float4(o[4],  o[5],  o[6],  o[7]);
            *(float4*)(dst +  8) = make_float4(o[8],  o[9],  o[10], o[11]);
            *(float4*)(dst + 12) = make_float4(o[12], o[13], o[14], o[15]);
        }

        const uint32_t aS = aSu[cur], bS = bSu[cur];
#pragma unroll
        for (int ks = 0; ks < 2; ks++) {
            uint32_t ah[2][4], al[2][4], bh[4][2], bl[4][2];
#pragma unroll
            for (int mt = 0; mt < 2; mt++) {
                uint32_t off = (uint32_t)(wm + mt * 16 + a_row) * 128 + ks * 32 + a_kof;
                LDSM_X4(ah[mt][0], ah[mt][1], ah[mt][2], ah[mt][3], aS + sw128(off));
            }
#pragma unroll
            for (int p = 0; p < 2; p++) {
                uint32_t r0, r1, r2, r3;
                uint32_t off = (uint32_t)(wn + p * 16 + b_row) * 128 + ks * 32 + b_kof;
                LDSM_X4(r0, r1, r2, r3, bS + sw128(off));
                bh[2 * p][0] = r0; bh[2 * p][1] = r1;
                bh[2 * p + 1][0] = r2; bh[2 * p + 1][1] = r3;
            }
#pragma unroll
            for (int mt = 0; mt < 2; mt++)
#pragma unroll
                for (int nt = 0; nt < 4; nt++)
                    mma16816(acc[mt][nt], ah[mt], bh[nt]);
#pragma unroll
            for (int p = 0; p < 2; p++) {
                uint32_t r0, r1, r2, r3;
                uint32_t off = (uint32_t)(wn + p * 16 + b_row) * 128 + 64 + ks * 32 + b_kof;
                LDSM_X4(r0, r1, r2, r3, bS + sw128(off));
                bl[2 * p][0] = r0; bl[2 * p][1] = r1;
                bl[2 * p + 1][0] = r2; bl[2 * p + 1][1] = r3;
            }
#pragma unroll
            for (int mt = 0; mt < 2; mt++)
#pragma unroll
                for (int nt = 0; nt < 4; nt++)
                    mma16816(acc[mt][nt], ah[mt], bl[nt]);
#pragma unroll
            for (int mt = 0; mt < 2; mt++) {
                uint32_t off = (uint32_t)(wm + mt * 16 + a_row) * 128 + 64 + ks * 32 + a_kof;
                LDSM_X4(al[mt][0], al[mt][1], al[mt][2], al[mt][3], aS + sw128(off));
            }
#pragma unroll
            for (int mt = 0; mt < 2; mt++)
#pragma unroll
                for (int nt = 0; nt < 4; nt++)
                    mma16816(acc[mt][nt], al[mt], bh[nt]);
        }
        __syncthreads();
        cur ^= 1;
    }

    // ---- epilogue ----
    const int g = lane >> 2, t = lane & 3;
    if (MODE == 2) {
#pragma unroll
        for (int mt = 0; mt < 2; mt++) {
            float sum0 = 0.0f, sum1 = 0.0f;
#pragma unroll
            for (int nt = 0; nt < 4; nt++) {
                const int colw = wn + nt * 8 + 2 * t;
                const long long row0 = m0 + wm + mt * 16 + g;
                float e0 = __expf(acc[mt][nt][0] * alpha);
                float e1 = __expf(acc[mt][nt][1] * alpha);
                float e2 = __expf(acc[mt][nt][2] * alpha);
                float e3 = __expf(acc[mt][nt][3] * alpha);
                const long long colg = n0 + colw;
                const long long ch = colg >> 5;
                const int wi = (int)(colg & 31);
                pack_store2(Cpk + row0 * ldCpk + ch * 128 + wi * 2, e0, e1);
                pack_store2(Cpk + (row0 + 8) * ldCpk + ch * 128 + wi * 2, e2, e3);
                sum0 += e0 + e1; sum1 += e2 + e3;
            }
            sum0 += __shfl_xor_sync(0xffffffffu, sum0, 1);
            sum0 += __shfl_xor_sync(0xffffffffu, sum0, 2);
            sum1 += __shfl_xor_sync(0xffffffffu, sum1, 1);
            sum1 += __shfl_xor_sync(0xffffffffu, sum1, 2);
            if (t == 0) {
                atomicAdd(&s_aux[wm + mt * 16 + g], sum0);
                atomicAdd(&s_aux[wm + mt * 16 + g + 8], sum1);
            }
        }
        __syncthreads();
        if (tid < 128)
            atomicAdd(&rs[rs_off + m0 + tid], s_aux[tid]);
    } else if (MODE == 1 || MODE == 3) {
#pragma unroll
        for (int mt = 0; mt < 2; mt++) {
            const float i0 = (MODE == 3) ? s_aux[wm + mt * 16 + g] : 1.0f;
            const float i1 = (MODE == 3) ? s_aux[wm + mt * 16 + g + 8] : 1.0f;
#pragma unroll
            for (int nt = 0; nt < 4; nt++) {
                const int colw = wn + nt * 8 + 2 * t;
                const long long row0 = m0 + wm + mt * 16 + g;
                const float b0 = (MODE == 1) ? s_bias[colw] : 0.0f;
                const float b1 = (MODE == 1) ? s_bias[colw + 1] : 0.0f;
                float v0 = acc[mt][nt][0] * i0 + b0;
                float v1 = acc[mt][nt][1] * i0 + b1;
                float v2 = acc[mt][nt][2] * i1 + b0;
                float v3 = acc[mt][nt][3] * i1 + b1;
                const long long colg = n0 + colw;
                const long long ch = colg >> 5;
                const int wi = (int)(colg & 31);
                pack_store2(Cpk + row0 * ldCpk + ch * 128 + wi * 2, v0, v1);
                pack_store2(Cpk + (row0 + 8) * ldCpk + ch * 128 + wi * 2, v2, v3);
            }
        }
    } else {
#pragma unroll
        for (int mt = 0; mt < 2; mt++) {
#pragma unroll
            for (int nt = 0; nt < 4; nt++) {
                const int colw = wn + nt * 8 + 2 * t;
                const float b0 = s_bias[colw], b1 = s_bias[colw + 1];
                const long long row0 = m0 + wm + mt * 16 + g;
                *(float2*)(Cf + row0 * (long long)ldc + n0 + colw) =
                    make_float2(acc[mt][nt][0] + b0, acc[mt][nt][1] + b1);
                *(float2*)(Cf + (row0 + 8) * (long long)ldc + n0 + colw) =
                    make_float2(acc[mt][nt][2] + b0, acc[mt][nt][3] + b1);
            }
        }
    }
}

// ---------------------------------------------------------------------------
// V transpose: vh fp32 [B,L,H,DK] -> vT packed [(b*H+h)][dk][L/32][128B]
// ---------------------------------------------------------------------------
__global__ void __launch_bounds__(256)
transpose_v_pk(const float* __restrict__ vh, uint8_t* __restrict__ vT)
{
    __shared__ float tsm[32][33];
    const int bh = blockIdx.z;
    const int b = bh >> 4, h = bh & 15;
    const int l0 = blockIdx.x * 32;
    const int d0 = blockIdx.y * 32;
    const int tid = threadIdx.x;
    const int tx = tid & 31;
    const int ty = tid >> 5;

    const float* src = vh + ((long long)b * L_ + l0) * HD_ + h * DK_ + d0;
#pragma unroll
    for (int i = 0; i < 32; i += 8)
        tsm[ty + i][tx] = src[(long long)(ty + i) * HD_ + tx];
    __syncthreads();

    const int lp = tid & 15;
#pragma unroll
    for (int it = 0; it < 2; it++) {
        const int d = (tid >> 4) + 16 * it;
        uint8_t* p = vT + ((long long)bh * 64 + d0 + d) * (L_ / 32 * 128)
                        + (l0 >> 5) * 128 + lp * 4;
        pack_store2(p, tsm[2 * lp][d], tsm[2 * lp + 1][d]);
    }
}

__global__ void zero_rs(float* __restrict__ rs)
{
    rs[blockIdx.x * 256 + threadIdx.x] = 0.0f;
}

// ---------------------------------------------------------------------------
// LayerNorm + residual
// ---------------------------------------------------------------------------
__global__ void __launch_bounds__(256)
ln_residual(const float* __restrict__ x, const float* __restrict__ res,
            const float* __restrict__ gam, const float* __restrict__ bet,
            float* __restrict__ out)
{
    const long long row = blockIdx.x;
    const float4* x4 = (const float4*)(x   + row * D_);
    const float4* r4 = (const float4*)(res + row * D_);
    const int tid = threadIdx.x;

    float4 v = x4[tid];
    float s  = (v.x + v.y) + (v.z + v.w);
    float sq = (v.x * v.x + v.y * v.y) + (v.z * v.z + v.w * v.w);
#pragma unroll
    for (int o = 16; o > 0; o >>= 1) {
        s  += __shfl_xor_sync(0xffffffffu, s,  o);
        sq += __shfl_xor_sync(0xffffffffu, sq, o);
    }
    __shared__ float ss[8], sqs[8];
    if ((tid & 31) == 0) { ss[tid >> 5] = s; sqs[tid >> 5] = sq; }
    __syncthreads();
    s  = (ss[0]  + ss[1])  + (ss[2]  + ss[3])  + (ss[4]  + ss[5])  + (ss[6]  + ss[7]);
    sq = (sqs[0] + sqs[1]) + (sqs[2] + sqs[3]) + (sqs[4] + sqs[5]) + (sqs[6] + sqs[7]);

    const float mean = s * (1.0f / D_);
    float var = sq * (1.0f / D_) - mean * mean;
    var = fmaxf(var, 0.0f);
    const float rstd = rsqrtf(var + LN_EPS_);

    float4 g  = ((const float4*)gam)[tid];
    float4 bt = ((const float4*)bet)[tid];
    float4 r  = r4[tid];
    float4 o;
    o.x = (v.x - mean) * rstd * g.x + bt.x + r.x;
    o.y = (v.y - mean) * rstd * g.y + bt.y + r.y;
    o.z = (v.z - mean) * rstd * g.z + bt.z + r.z;
    o.w = (v.w - mean) * rstd * g.w + bt.w + r.w;
    ((float4*)(out + row * D_))[tid] = o;
}

// ---------------------------------------------------------------------------
// Launch
// ---------------------------------------------------------------------------
extern "C" void kernel_launch(void* const* d_in, const int* in_sizes, int n_in,
                              void* d_out, int out_size)
{
    (void)in_sizes; (void)n_in; (void)out_size;
    const float* q  = (const float*)d_in[0];
    const float* k  = (const float*)d_in[1];
    const float* v  = (const float*)d_in[2];
    const float* wq = (const float*)d_in[3];
    const float* bq = (const float*)d_in[4];
    const float* wk = (const float*)d_in[5];
    const float* bk = (const float*)d_in[6];
    const float* wv = (const float*)d_in[7];
    const float* bv = (const float*)d_in[8];
    const float* wo = (const float*)d_in[9];
    const float* bo = (const float*)d_in[10];
    const float* lg = (const float*)d_in[11];
    const float* lb = (const float*)d_in[12];

    float* out  = (float*)d_out;
    float* attn = out + (long long)B_ * L_ * D_;
    uint8_t* attn_b = (uint8_t*)attn;

    uint8_t *qpk, *kpk, *vpk, *wqpk, *wkpk, *wvpk, *wopk, *qhpk, *khpk, *vTpk, *oapk;
    float *vh, *op, *rs;
    cudaGetSymbolAddress((void**)&qpk,  g_qpk);
    cudaGetSymbolAddress((void**)&kpk,  g_kpk);
    cudaGetSymbolAddress((void**)&vpk,  g_vpk);
    cudaGetSymbolAddress((void**)&wqpk, g_wqpk);
    cudaGetSymbolAddress((void**)&wkpk, g_wkpk);
    cudaGetSymbolAddress((void**)&wvpk, g_wvpk);
    cudaGetSymbolAddress((void**)&wopk, g_wopk);
    cudaGetSymbolAddress((void**)&qhpk, g_qhpk);
    cudaGetSymbolAddress((void**)&khpk, g_khpk);
    cudaGetSymbolAddress((void**)&vTpk, g_vTpk);
    cudaGetSymbolAddress((void**)&oapk, g_oapk);
    cudaGetSymbolAddress((void**)&vh,   g_vh);
    cudaGetSymbolAddress((void**)&op,   g_op);
    cudaGetSymbolAddress((void**)&rs,   g_rs);

    const int SMEMB = 2 * 24576 + 1024;
    cudaFuncSetAttribute((const void*)pk_gemm<0>, cudaFuncAttributeMaxDynamicSharedMemorySize, SMEMB);
    cudaFuncSetAttribute((const void*)pk_gemm<1>, cudaFuncAttributeMaxDynamicSharedMemorySize, SMEMB);
    cudaFuncSetAttribute((const void*)pk_gemm<2>, cudaFuncAttributeMaxDynamicSharedMemorySize, SMEMB);
    cudaFuncSetAttribute((const void*)pk_gemm<3>, cudaFuncAttributeMaxDynamicSharedMemorySize, SMEMB);

    dim3 blk(256);

    zero_rs<<<NROWS_ATTN / 256, blk>>>(rs);

    // pack inputs + weights (batched)
    pack_split3<<<dim3(MROWS_ * D_ / 4 / 256, 1, 3), blk>>>(q, k, v, qpk, kpk, vpk, D_);
    pack_split3<<<dim3(HD_ * D_ / 4 / 256, 1, 3), blk>>>(wq, wk, wv, wqpk, wkpk, wvpk, D_);
    pack_split1<<<D_ * HD_ / 4 / 256, blk>>>(wo, wopk, HD_);

    const long long ld32 = 32 * 128;   // 4096B row (K=1024)
    const long long ld64 = 64 * 128;   // 8192B row (K=2048)

    // QKV projections (K=1024 -> 32 chunks)
    dim3 gproj(HD_ / 64, MROWS_ / 128, 1);
    pk_gemm<1><<<gproj, blk, SMEMB>>>(qpk, wqpk, bq, nullptr, qhpk, nullptr,
        32, ld32, ld32, 0, ld32, 1,
        0, 0, 0, 0, 0, 0, 0, 0, 0, 0, 1.0f);
    pk_gemm<1><<<gproj, blk, SMEMB>>>(kpk, wkpk, bk, nullptr, khpk, nullptr,
        32, ld32, ld32, 0, ld32, 1,
        0, 0, 0, 0, 0, 0, 0, 0, 0, 0, 1.0f);
    pk_gemm<0><<<gproj, blk, SMEMB>>>(vpk, wvpk, bv, vh, nullptr, nullptr,
        32, ld32, ld32, HD_, 0, 1,
        0, 0, 0, 0, 0, 0, 0, 0, 0, 0, 1.0f);

    transpose_v_pk<<<dim3(L_ / 32, DK_ / 32, B_ * H_), blk>>>(vh, vTpk);

    // Scores (K=64 -> 2 chunks): attn[(h*B+b)] = exp((qh@kh^T)/8) packed + rowsums
    dim3 gsc(L_ / 64, L_ / 128, B_ * H_);
    pk_gemm<2><<<gsc, blk, SMEMB>>>(qhpk, khpk, nullptr, nullptr, attn_b, rs,
        2, ld32, ld32, 0, ld64, H_,
        (long long)L_ * ld32, 256,
        (long long)L_ * ld32, 256,
        0, 0,
        (long long)L_ * L_ * 4, (long long)B_ * L_ * L_ * 4,
        (long long)L_, (long long)B_ * L_,
        0.125f);

    // PV (K=2048 -> 64 chunks): in-place normalized P + oa packed
    dim3 gpv(1, L_ / 128, B_ * H_);
    pk_gemm<3><<<gpv, blk, SMEMB>>>(attn_b, vTpk, nullptr, attn, oapk, rs,
        64, ld64, ld64, L_, ld32, H_,
        (long long)L_ * L_ * 4, (long long)B_ * L_ * L_ * 4,
        (long long)DK_ * ld64 * H_, (long long)DK_ * ld64,
        (long long)L_ * L_, (long long)B_ * L_ * L_,
        (long long)L_ * ld32, 256,
        (long long)L_, (long long)B_ * L_,
        1.0f);

    // Output projection (K=1024 -> 32 chunks)
    dim3 gop(D_ / 64, MROWS_ / 128, 1);
    pk_gemm<0><<<gop, blk, SMEMB>>>(oapk, wopk, bo, op, nullptr, nullptr,
        32, ld32, ld32, D_, 0, 1,
        0, 0, 0, 0, 0, 0, 0, 0, 0, 0, 1.0f);

    // LayerNorm + residual
    ln_residual<<<MROWS_, blk>>>(op, q, lg, lb, out);
}

// round 9
// speedup vs baseline: 1.1289x; 1.0450x over previous
#include <cuda_runtime.h>
#include <cuda_bf16.h>
#include <stdint.h>

#define B_   4
#define L_   2048
#define D_   1024
#define H_   16
#define DK_  64
#define HD_  1024
#define MROWS_ 8192
#define LN_EPS_ 1e-5f
#define NROWS_ATTN (B_ * H_ * L_)

// ---------------------------------------------------------------------------
// Scratch (device globals). Packed split-bf16: [M][K/32][32 hi | 32 lo] 128B.
// ---------------------------------------------------------------------------
__device__ __align__(256) uint8_t g_qpk [(long long)MROWS_ * D_ * 4];
__device__ __align__(256) uint8_t g_kpk [(long long)MROWS_ * D_ * 4];
__device__ __align__(256) uint8_t g_vpk [(long long)MROWS_ * D_ * 4];
__device__ __align__(256) uint8_t g_wqpk[(long long)HD_ * D_ * 4];
__device__ __align__(256) uint8_t g_wkpk[(long long)HD_ * D_ * 4];
__device__ __align__(256) uint8_t g_wvpk[(long long)HD_ * D_ * 4];
__device__ __align__(256) uint8_t g_wopk[(long long)D_ * HD_ * 4];
__device__ __align__(256) uint8_t g_qhpk[(long long)MROWS_ * HD_ * 4];
__device__ __align__(256) uint8_t g_khpk[(long long)MROWS_ * HD_ * 4];
__device__ __align__(256) uint8_t g_vTpk[(long long)B_ * H_ * DK_ * L_ * 4];
__device__ __align__(256) uint8_t g_oapk[(long long)MROWS_ * HD_ * 4];
__device__ float g_vh[MROWS_ * HD_];
__device__ float g_op[MROWS_ * HD_];
__device__ float g_rs[NROWS_ATTN];

// ---------------------------------------------------------------------------
// helpers
// ---------------------------------------------------------------------------
__device__ __forceinline__ uint32_t smem_u32(const void* p) {
    uint32_t a;
    asm("{ .reg .u64 t; cvta.to.shared.u64 t, %1; cvt.u32.u64 %0, t; }" : "=r"(a) : "l"(p));
    return a;
}
__device__ __forceinline__ uint32_t sw128(uint32_t off) {
    return off ^ ((off >> 3) & 0x70);
}
__device__ __forceinline__ void cpa16(uint32_t dst, const void* src) {
    asm volatile("cp.async.cg.shared.global [%0], [%1], 16;" :: "r"(dst), "l"(src));
}
#define CP_COMMIT() asm volatile("cp.async.commit_group;" ::: "memory")
#define CP_WAIT0()  asm volatile("cp.async.wait_group 0;" ::: "memory")
#define CP_WAIT1()  asm volatile("cp.async.wait_group 1;" ::: "memory")
#define LDSM_X4(r0, r1, r2, r3, addr)                                      \
    asm volatile("ldmatrix.sync.aligned.m8n8.x4.shared.b16 "               \
                 "{%0,%1,%2,%3}, [%4];"                                    \
                 : "=r"(r0), "=r"(r1), "=r"(r2), "=r"(r3) : "r"(addr))

__device__ __forceinline__ void mma16816(float* d, const uint32_t* a, const uint32_t* b) {
    asm volatile(
        "mma.sync.aligned.m16n8k16.row.col.f32.bf16.bf16.f32 "
        "{%0,%1,%2,%3}, {%4,%5,%6,%7}, {%8,%9}, {%0,%1,%2,%3};"
        : "+f"(d[0]), "+f"(d[1]), "+f"(d[2]), "+f"(d[3])
        : "r"(a[0]), "r"(a[1]), "r"(a[2]), "r"(a[3]), "r"(b[0]), "r"(b[1]));
}

__device__ __forceinline__ void pack_store2(uint8_t* p, float v0, float v1) {
    __nv_bfloat162 h = __floats2bfloat162_rn(v0, v1);
    float2 f = __bfloat1622float2(h);
    __nv_bfloat162 l = __floats2bfloat162_rn(v0 - f.x, v1 - f.y);
    *(uint32_t*)p = *(uint32_t*)&h;
    *(uint32_t*)(p + 64) = *(uint32_t*)&l;
}
__device__ __forceinline__ void pack_store4(uint8_t* p, float4 v) {
    __nv_bfloat162 h0 = __floats2bfloat162_rn(v.x, v.y);
    __nv_bfloat162 h1 = __floats2bfloat162_rn(v.z, v.w);
    float2 f0 = __bfloat1622float2(h0), f1 = __bfloat1622float2(h1);
    __nv_bfloat162 l0 = __floats2bfloat162_rn(v.x - f0.x, v.y - f0.y);
    __nv_bfloat162 l1 = __floats2bfloat162_rn(v.z - f1.x, v.w - f1.y);
    uint2 hu, lu;
    hu.x = *(uint32_t*)&h0; hu.y = *(uint32_t*)&h1;
    lu.x = *(uint32_t*)&l0; lu.y = *(uint32_t*)&l1;
    *(uint2*)p = hu;
    *(uint2*)(p + 64) = lu;
}
__device__ __forceinline__ void combine8(const uint4 h, const uint4 l, float inv, float* out) {
    const uint32_t hu[4] = { h.x, h.y, h.z, h.w };
    const uint32_t lu[4] = { l.x, l.y, l.z, l.w };
#pragma unroll
    for (int j = 0; j < 4; j++) {
        __nv_bfloat162 hb = *(const __nv_bfloat162*)&hu[j];
        __nv_bfloat162 lb = *(const __nv_bfloat162*)&lu[j];
        float2 hf = __bfloat1622float2(hb), lf = __bfloat1622float2(lb);
        out[2 * j]     = (hf.x + lf.x) * inv;
        out[2 * j + 1] = (hf.y + lf.y) * inv;
    }
}

// ---------------------------------------------------------------------------
// pack fp32 [M,K] -> packed split bf16 ; batched over 3 tensors via blockIdx.z
// ---------------------------------------------------------------------------
__global__ void __launch_bounds__(256)
pack_split3(const float* __restrict__ s0, const float* __restrict__ s1,
            const float* __restrict__ s2,
            uint8_t* __restrict__ d0, uint8_t* __restrict__ d1,
            uint8_t* __restrict__ d2, int K)
{
    const float* src = (blockIdx.z == 0) ? s0 : (blockIdx.z == 1) ? s1 : s2;
    uint8_t* dst = (blockIdx.z == 0) ? d0 : (blockIdx.z == 1) ? d1 : d2;
    const long long idx = (long long)blockIdx.x * 256 + threadIdx.x;
    const int perRow = K >> 2;
    const long long m = idx / perRow;
    const int j = (int)(idx - m * perRow);
    float4 v = *(const float4*)(src + m * K + j * 4);
    const int e0 = j * 4;
    uint8_t* p = dst + (m * (K >> 5) + (e0 >> 5)) * 128 + (e0 & 31) * 2;
    pack_store4(p, v);
}
__global__ void __launch_bounds__(256)
pack_split1(const float* __restrict__ src, uint8_t* __restrict__ dst, int K)
{
    const long long idx = (long long)blockIdx.x * 256 + threadIdx.x;
    const int perRow = K >> 2;
    const long long m = idx / perRow;
    const int j = (int)(idx - m * perRow);
    float4 v = *(const float4*)(src + m * K + j * 4);
    const int e0 = j * 4;
    uint8_t* p = dst + (m * (K >> 5) + (e0 >> 5)) * 128 + (e0 & 31) * 2;
    pack_store4(p, v);
}

// ---------------------------------------------------------------------------
// Packed split-bf16 GEMM. CTA tile 128 x TN, 32-K chunks, 8 warps as 4x2
// (warp tile 32 x TN/2), 2 CTAs/SM. Split passes ordered hh -> lh -> hl so
// B-hi fragments die before B-lo loads (register pressure).
// MODE 0: C fp32 + bias.  MODE 1: C packed + bias.
// MODE 2: exp(alpha*acc) -> packed + rowsum atomics.
// MODE 3: A staged tiles -> normalized fp32 P write; epilogue *1/rowsum -> packed.
// ---------------------------------------------------------------------------
template<int TN, int MODE>
__global__ void __launch_bounds__(256, 2)
pk_gemm(const uint8_t* Apk, const uint8_t* __restrict__ Bpk,
        const float* __restrict__ bias,
        float* Cf, uint8_t* Cpk, float* rs,
        int nchunks, long long ldA, long long ldB, int ldc, long long ldCpk,
        int zdiv,
        long long sAo, long long sAi, long long sBo, long long sBi,
        long long sCfO, long long sCfI, long long sCpO, long long sCpI,
        long long rsO, long long rsI, float alpha)
{
    constexpr int NT = TN / 16;            // n8-tiles per warp
    constexpr int NB = TN / 32;            // B cp.async per thread per chunk
    constexpr int STAGE = 16384 + TN * 128;

    extern __shared__ uint8_t dyn_raw[];
    __shared__ float s_bias[TN];
    __shared__ float s_aux[128];

    const int tid = threadIdx.x, wid = tid >> 5, lane = tid & 31;
    const int z = blockIdx.z, zo = z / zdiv, zi = z - zo * zdiv;
    Apk += zo * sAo + zi * sAi;
    Bpk += zo * sBo + zi * sBi;
    if (MODE == 0 || MODE == 3) Cf += zo * sCfO + zi * sCfI;
    if (MODE != 0) Cpk += zo * sCpO + zi * sCpI;
    const long long rs_off = zo * rsO + zi * rsI;

    const long long m0 = (long long)blockIdx.y * 128;
    const long long n0 = (long long)blockIdx.x * TN;

    uint32_t raw = smem_u32(dyn_raw);
    uint32_t base = (raw + 1023u) & ~1023u;
    uint8_t* dsm = dyn_raw + (base - raw);
    uint8_t* smA[2] = { dsm, dsm + STAGE };
    const uint32_t aSu[2] = { base, base + STAGE };
    const uint32_t bSu[2] = { base + 16384, base + STAGE + 16384 };

    if (MODE == 0 || MODE == 1) {
        for (int i = tid; i < TN; i += 256) s_bias[i] = bias ? bias[n0 + i] : 0.0f;
    }
    if (MODE == 2) { if (tid < 128) s_aux[tid] = 0.0f; }
    if (MODE == 3) { if (tid < 128) s_aux[tid] = 1.0f / rs[rs_off + m0 + tid]; }

    float acc[2][NT][4];
#pragma unroll
    for (int i = 0; i < 2; i++)
#pragma unroll
        for (int j = 0; j < NT; j++)
#pragma unroll
            for (int e = 0; e < 4; e++) acc[i][j][e] = 0.0f;

    const uint32_t a_row = (uint32_t)((lane & 7) + (lane & 8));
    const uint32_t a_kof = (uint32_t)(((lane >> 4) & 1) * 16);
    const uint32_t b_row = (uint32_t)((lane & 7) + ((lane >> 4) & 1) * 8);
    const uint32_t b_kof = (uint32_t)(((lane >> 3) & 1) * 16);
    const int wm = (wid & 3) * 32;
    const int wn = (wid >> 2) * (TN / 2);

    auto prefetch = [&](int s, int c) {
        const uint8_t* Ab = Apk + (long long)c * 128;
#pragma unroll
        for (int i = 0; i < 4; i++) {
            const int idx = i * 256 + tid, row = idx >> 3, g = idx & 7;
            cpa16(aSu[s] + sw128((uint32_t)(row * 128 + g * 16)),
                  Ab + (m0 + row) * ldA + g * 16);
        }
        const uint8_t* Bb = Bpk + (long long)c * 128;
#pragma unroll
        for (int i = 0; i < NB; i++) {
            const int idx = i * 256 + tid, row = idx >> 3, g = idx & 7;
            cpa16(bSu[s] + sw128((uint32_t)(row * 128 + g * 16)),
                  Bb + (n0 + row) * ldB + g * 16);
        }
        CP_COMMIT();
    };

    prefetch(0, 0);
    int cur = 0;
    for (int c = 0; c < nchunks; c++) {
        if (c + 1 < nchunks) {
            prefetch(cur ^ 1, c + 1);
            CP_WAIT1();
        } else {
            CP_WAIT0();
        }
        __syncthreads();

        if (MODE == 3) {
            // reconstruct normalized fp32 P for this 32-K chunk (in place)
            const int r = tid >> 1, hh = tid & 1;
            const uint8_t* sa = smA[cur];
            const float inv = s_aux[r];
            uint4 h0 = *(const uint4*)(sa + sw128((uint32_t)(r * 128 + hh * 32)));
            uint4 h1 = *(const uint4*)(sa + sw128((uint32_t)(r * 128 + hh * 32 + 16)));
            uint4 l0 = *(const uint4*)(sa + sw128((uint32_t)(r * 128 + 64 + hh * 32)));
            uint4 l1 = *(const uint4*)(sa + sw128((uint32_t)(r * 128 + 64 + hh * 32 + 16)));
            float o[16];
            combine8(h0, l0, inv, o);
            combine8(h1, l1, inv, o + 8);
            float* dst = Cf + (m0 + r) * (long long)ldc + c * 32 + hh * 16;
            *(float4*)(dst +  0) = make_float4(o[0],  o[1],  o[2],  o[3]);
            *(float4*)(dst +  4) = make_float4(o[4],  o[5],  o[6],  o[7]);
            *(float4*)(dst +  8) = make_float4(o[8],  o[9],  o[10], o[11]);
            *(float4*)(dst + 12) = make_float4(o[12], o[13], o[14], o[15]);
        }

        const uint32_t aS = aSu[cur], bS = bSu[cur];
#pragma unroll
        for (int ks = 0; ks < 2; ks++) {
            uint32_t ah[2][4], al[2][4], bf[NT][2];
            // A hi
#pragma unroll
            for (int mt = 0; mt < 2; mt++) {
                uint32_t off = (uint32_t)(wm + mt * 16 + a_row) * 128 + ks * 32 + a_kof;
                LDSM_X4(ah[mt][0], ah[mt][1], ah[mt][2], ah[mt][3], aS + sw128(off));
            }
            // B hi
#pragma unroll
            for (int p = 0; p < NT / 2; p++) {
                uint32_t r0, r1, r2, r3;
                uint32_t off = (uint32_t)(wn + p * 16 + b_row) * 128 + ks * 32 + b_kof;
                LDSM_X4(r0, r1, r2, r3, bS + sw128(off));
                bf[2 * p][0] = r0; bf[2 * p][1] = r1;
                bf[2 * p + 1][0] = r2; bf[2 * p + 1][1] = r3;
            }
            // pass 1: hi x hi
#pragma unroll
            for (int mt = 0; mt < 2; mt++)
#pragma unroll
                for (int nt = 0; nt < NT; nt++)
                    mma16816(acc[mt][nt], ah[mt], bf[nt]);
            // A lo
#pragma unroll
            for (int mt = 0; mt < 2; mt++) {
                uint32_t off = (uint32_t)(wm + mt * 16 + a_row) * 128 + 64 + ks * 32 + a_kof;
                LDSM_X4(al[mt][0], al[mt][1], al[mt][2], al[mt][3], aS + sw128(off));
            }
            // pass 2: lo x hi  (B-hi dies after this)
#pragma unroll
            for (int mt = 0; mt < 2; mt++)
#pragma unroll
                for (int nt = 0; nt < NT; nt++)
                    mma16816(acc[mt][nt], al[mt], bf[nt]);
            // B lo (reuse bf)
#pragma unroll
            for (int p = 0; p < NT / 2; p++) {
                uint32_t r0, r1, r2, r3;
                uint32_t off = (uint32_t)(wn + p * 16 + b_row) * 128 + 64 + ks * 32 + b_kof;
                LDSM_X4(r0, r1, r2, r3, bS + sw128(off));
                bf[2 * p][0] = r0; bf[2 * p][1] = r1;
                bf[2 * p + 1][0] = r2; bf[2 * p + 1][1] = r3;
            }
            // pass 3: hi x lo
#pragma unroll
            for (int mt = 0; mt < 2; mt++)
#pragma unroll
                for (int nt = 0; nt < NT; nt++)
                    mma16816(acc[mt][nt], ah[mt], bf[nt]);
        }
        __syncthreads();
        cur ^= 1;
    }

    // ---- epilogue ----
    const int g = lane >> 2, t = lane & 3;
    if (MODE == 2) {
#pragma unroll
        for (int mt = 0; mt < 2; mt++) {
            float sum0 = 0.0f, sum1 = 0.0f;
#pragma unroll
            for (int nt = 0; nt < NT; nt++) {
                const int colw = wn + nt * 8 + 2 * t;
                const long long row0 = m0 + wm + mt * 16 + g;
                float e0 = __expf(acc[mt][nt][0] * alpha);
                float e1 = __expf(acc[mt][nt][1] * alpha);
                float e2 = __expf(acc[mt][nt][2] * alpha);
                float e3 = __expf(acc[mt][nt][3] * alpha);
                const long long colg = n0 + colw;
                const long long ch = colg >> 5;
                const int wi = (int)(colg & 31);
                pack_store2(Cpk + row0 * ldCpk + ch * 128 + wi * 2, e0, e1);
                pack_store2(Cpk + (row0 + 8) * ldCpk + ch * 128 + wi * 2, e2, e3);
                sum0 += e0 + e1; sum1 += e2 + e3;
            }
            sum0 += __shfl_xor_sync(0xffffffffu, sum0, 1);
            sum0 += __shfl_xor_sync(0xffffffffu, sum0, 2);
            sum1 += __shfl_xor_sync(0xffffffffu, sum1, 1);
            sum1 += __shfl_xor_sync(0xffffffffu, sum1, 2);
            if (t == 0) {
                atomicAdd(&s_aux[wm + mt * 16 + g], sum0);
                atomicAdd(&s_aux[wm + mt * 16 + g + 8], sum1);
            }
        }
        __syncthreads();
        if (tid < 128)
            atomicAdd(&rs[rs_off + m0 + tid], s_aux[tid]);
    } else if (MODE == 1 || MODE == 3) {
#pragma unroll
        for (int mt = 0; mt < 2; mt++) {
            const float i0 = (MODE == 3) ? s_aux[wm + mt * 16 + g] : 1.0f;
            const float i1 = (MODE == 3) ? s_aux[wm + mt * 16 + g + 8] : 1.0f;
#pragma unroll
            for (int nt = 0; nt < NT; nt++) {
                const int colw = wn + nt * 8 + 2 * t;
                const long long row0 = m0 + wm + mt * 16 + g;
                const float b0 = (MODE == 1) ? s_bias[colw] : 0.0f;
                const float b1 = (MODE == 1) ? s_bias[colw + 1] : 0.0f;
                float v0 = acc[mt][nt][0] * i0 + b0;
                float v1 = acc[mt][nt][1] * i0 + b1;
                float v2 = acc[mt][nt][2] * i1 + b0;
                float v3 = acc[mt][nt][3] * i1 + b1;
                const long long colg = n0 + colw;
                const long long ch = colg >> 5;
                const int wi = (int)(colg & 31);
                pack_store2(Cpk + row0 * ldCpk + ch * 128 + wi * 2, v0, v1);
                pack_store2(Cpk + (row0 + 8) * ldCpk + ch * 128 + wi * 2, v2, v3);
            }
        }
    } else {
#pragma unroll
        for (int mt = 0; mt < 2; mt++) {
#pragma unroll
            for (int nt = 0; nt < NT; nt++) {
                const int colw = wn + nt * 8 + 2 * t;
                const float b0 = s_bias[colw], b1 = s_bias[colw + 1];
                const long long row0 = m0 + wm + mt * 16 + g;
                *(float2*)(Cf + row0 * (long long)ldc + n0 + colw) =
                    make_float2(acc[mt][nt][0] + b0, acc[mt][nt][1] + b1);
                *(float2*)(Cf + (row0 + 8) * (long long)ldc + n0 + colw) =
                    make_float2(acc[mt][nt][2] + b0, acc[mt][nt][3] + b1);
            }
        }
    }
}

// ---------------------------------------------------------------------------
// V transpose: vh fp32 [B,L,H,DK] -> vT packed [(b*H+h)][dk][L/32][128B]
// ---------------------------------------------------------------------------
__global__ void __launch_bounds__(256)
transpose_v_pk(const float* __restrict__ vh, uint8_t* __restrict__ vT)
{
    __shared__ float tsm[32][33];
    const int bh = blockIdx.z;
    const int b = bh >> 4, h = bh & 15;
    const int l0 = blockIdx.x * 32;
    const int d0 = blockIdx.y * 32;
    const int tid = threadIdx.x;
    const int tx = tid & 31;
    const int ty = tid >> 5;

    const float* src = vh + ((long long)b * L_ + l0) * HD_ + h * DK_ + d0;
#pragma unroll
    for (int i = 0; i < 32; i += 8)
        tsm[ty + i][tx] = src[(long long)(ty + i) * HD_ + tx];
    __syncthreads();

    const int lp = tid & 15;
#pragma unroll
    for (int it = 0; it < 2; it++) {
        const int d = (tid >> 4) + 16 * it;
        uint8_t* p = vT + ((long long)bh * 64 + d0 + d) * (L_ / 32 * 128)
                        + (l0 >> 5) * 128 + lp * 4;
        pack_store2(p, tsm[2 * lp][d], tsm[2 * lp + 1][d]);
    }
}

__global__ void zero_rs(float* __restrict__ rs)
{
    rs[blockIdx.x * 256 + threadIdx.x] = 0.0f;
}

// ---------------------------------------------------------------------------
// LayerNorm + residual
// ---------------------------------------------------------------------------
__global__ void __launch_bounds__(256)
ln_residual(const float* __restrict__ x, const float* __restrict__ res,
            const float* __restrict__ gam, const float* __restrict__ bet,
            float* __restrict__ out)
{
    const long long row = blockIdx.x;
    const float4* x4 = (const float4*)(x   + row * D_);
    const float4* r4 = (const float4*)(res + row * D_);
    const int tid = threadIdx.x;

    float4 v = x4[tid];
    float s  = (v.x + v.y) + (v.z + v.w);
    float sq = (v.x * v.x + v.y * v.y) + (v.z * v.z + v.w * v.w);
#pragma unroll
    for (int o = 16; o > 0; o >>= 1) {
        s  += __shfl_xor_sync(0xffffffffu, s,  o);
        sq += __shfl_xor_sync(0xffffffffu, sq, o);
    }
    __shared__ float ss[8], sqs[8];
    if ((tid & 31) == 0) { ss[tid >> 5] = s; sqs[tid >> 5] = sq; }
    __syncthreads();
    s  = (ss[0]  + ss[1])  + (ss[2]  + ss[3])  + (ss[4]  + ss[5])  + (ss[6]  + ss[7]);
    sq = (sqs[0] + sqs[1]) + (sqs[2] + sqs[3]) + (sqs[4] + sqs[5]) + (sqs[6] + sqs[7]);

    const float mean = s * (1.0f / D_);
    float var = sq * (1.0f / D_) - mean * mean;
    var = fmaxf(var, 0.0f);
    const float rstd = rsqrtf(var + LN_EPS_);

    float4 g  = ((const float4*)gam)[tid];
    float4 bt = ((const float4*)bet)[tid];
    float4 r  = r4[tid];
    float4 o;
    o.x = (v.x - mean) * rstd * g.x + bt.x + r.x;
    o.y = (v.y - mean) * rstd * g.y + bt.y + r.y;
    o.z = (v.z - mean) * rstd * g.z + bt.z + r.z;
    o.w = (v.w - mean) * rstd * g.w + bt.w + r.w;
    ((float4*)(out + row * D_))[tid] = o;
}

// ---------------------------------------------------------------------------
// Launch
// ---------------------------------------------------------------------------
extern "C" void kernel_launch(void* const* d_in, const int* in_sizes, int n_in,
                              void* d_out, int out_size)
{
    (void)in_sizes; (void)n_in; (void)out_size;
    const float* q  = (const float*)d_in[0];
    const float* k  = (const float*)d_in[1];
    const float* v  = (const float*)d_in[2];
    const float* wq = (const float*)d_in[3];
    const float* bq = (const float*)d_in[4];
    const float* wk = (const float*)d_in[5];
    const float* bk = (const float*)d_in[6];
    const float* wv = (const float*)d_in[7];
    const float* bv = (const float*)d_in[8];
    const float* wo = (const float*)d_in[9];
    const float* bo = (const float*)d_in[10];
    const float* lg = (const float*)d_in[11];
    const float* lb = (const float*)d_in[12];

    float* out  = (float*)d_out;
    float* attn = out + (long long)B_ * L_ * D_;
    uint8_t* attn_b = (uint8_t*)attn;

    uint8_t *qpk, *kpk, *vpk, *wqpk, *wkpk, *wvpk, *wopk, *qhpk, *khpk, *vTpk, *oapk;
    float *vh, *op, *rs;
    cudaGetSymbolAddress((void**)&qpk,  g_qpk);
    cudaGetSymbolAddress((void**)&kpk,  g_kpk);
    cudaGetSymbolAddress((void**)&vpk,  g_vpk);
    cudaGetSymbolAddress((void**)&wqpk, g_wqpk);
    cudaGetSymbolAddress((void**)&wkpk, g_wkpk);
    cudaGetSymbolAddress((void**)&wvpk, g_wvpk);
    cudaGetSymbolAddress((void**)&wopk, g_wopk);
    cudaGetSymbolAddress((void**)&qhpk, g_qhpk);
    cudaGetSymbolAddress((void**)&khpk, g_khpk);
    cudaGetSymbolAddress((void**)&vTpk, g_vTpk);
    cudaGetSymbolAddress((void**)&oapk, g_oapk);
    cudaGetSymbolAddress((void**)&vh,   g_vh);
    cudaGetSymbolAddress((void**)&op,   g_op);
    cudaGetSymbolAddress((void**)&rs,   g_rs);

    const int SMEM128 = 2 * (16384 + 128 * 128) + 1024;   // 66560
    const int SMEM64  = 2 * (16384 + 64 * 128) + 1024;    // 50176
    cudaFuncSetAttribute((const void*)pk_gemm<128, 0>, cudaFuncAttributeMaxDynamicSharedMemorySize, SMEM128);
    cudaFuncSetAttribute((const void*)pk_gemm<128, 1>, cudaFuncAttributeMaxDynamicSharedMemorySize, SMEM128);
    cudaFuncSetAttribute((const void*)pk_gemm<128, 2>, cudaFuncAttributeMaxDynamicSharedMemorySize, SMEM128);
    cudaFuncSetAttribute((const void*)pk_gemm<64, 3>,  cudaFuncAttributeMaxDynamicSharedMemorySize, SMEM64);

    dim3 blk(256);

    zero_rs<<<NROWS_ATTN / 256, blk>>>(rs);

    // pack inputs + weights (batched)
    pack_split3<<<dim3(MROWS_ * D_ / 4 / 256, 1, 3), blk>>>(q, k, v, qpk, kpk, vpk, D_);
    pack_split3<<<dim3(HD_ * D_ / 4 / 256, 1, 3), blk>>>(wq, wk, wv, wqpk, wkpk, wvpk, D_);
    pack_split1<<<D_ * HD_ / 4 / 256, blk>>>(wo, wopk, HD_);

    const long long ld32 = 32 * 128;   // 4096B row (K=1024)
    const long long ld64 = 64 * 128;   // 8192B row (K=2048)

    // QKV projections (K=1024 -> 32 chunks), 128x128 tiles
    dim3 gproj(HD_ / 128, MROWS_ / 128, 1);
    pk_gemm<128, 1><<<gproj, blk, SMEM128>>>(qpk, wqpk, bq, nullptr, qhpk, nullptr,
        32, ld32, ld32, 0, ld32, 1,
        0, 0, 0, 0, 0, 0, 0, 0, 0, 0, 1.0f);
    pk_gemm<128, 1><<<gproj, blk, SMEM128>>>(kpk, wkpk, bk, nullptr, khpk, nullptr,
        32, ld32, ld32, 0, ld32, 1,
        0, 0, 0, 0, 0, 0, 0, 0, 0, 0, 1.0f);
    pk_gemm<128, 0><<<gproj, blk, SMEM128>>>(vpk, wvpk, bv, vh, nullptr, nullptr,
        32, ld32, ld32, HD_, 0, 1,
        0, 0, 0, 0, 0, 0, 0, 0, 0, 0, 1.0f);

    transpose_v_pk<<<dim3(L_ / 32, DK_ / 32, B_ * H_), blk>>>(vh, vTpk);

    // Scores (K=64 -> 2 chunks), 128x128 tiles
    dim3 gsc(L_ / 128, L_ / 128, B_ * H_);
    pk_gemm<128, 2><<<gsc, blk, SMEM128>>>(qhpk, khpk, nullptr, nullptr, attn_b, rs,
        2, ld32, ld32, 0, ld64, H_,
        (long long)L_ * ld32, 256,
        (long long)L_ * ld32, 256,
        0, 0,
        (long long)L_ * L_ * 4, (long long)B_ * L_ * L_ * 4,
        (long long)L_, (long long)B_ * L_,
        0.125f);

    // PV (K=2048 -> 64 chunks), 128x64 tiles: in-place normalized P + oa packed
    dim3 gpv(1, L_ / 128, B_ * H_);
    pk_gemm<64, 3><<<gpv, blk, SMEM64>>>(attn_b, vTpk, nullptr, attn, oapk, rs,
        64, ld64, ld64, L_, ld32, H_,
        (long long)L_ * L_ * 4, (long long)B_ * L_ * L_ * 4,
        (long long)DK_ * ld64 * H_, (long long)DK_ * ld64,
        (long long)L_ * L_, (long long)B_ * L_ * L_,
        (long long)L_ * ld32, 256,
        (long long)L_, (long long)B_ * L_,
        1.0f);

    // Output projection (K=1024 -> 32 chunks), 128x128 tiles
    dim3 gop(D_ / 128, MROWS_ / 128, 1);
    pk_gemm<128, 0><<<gop, blk, SMEM128>>>(oapk, wopk, bo, op, nullptr, nullptr,
        32, ld32, ld32, D_, 0, 1,
        0, 0, 0, 0, 0, 0, 0, 0, 0, 0, 1.0f);

    // LayerNorm + residual
    ln_residual<<<MROWS_, blk>>>(op, q, lg, lb, out);
}